// round 1
// baseline (speedup 1.0000x reference)
#include <cuda_runtime.h>
#include <math.h>

// Problem constants (asserted implicitly by the dataset shapes)
#define BMAX 4
#define SMAX 4096
#define DMAX 1024
#define EMAX 8
#define PPART 32          // partial-sum parts for column mean
#define NCH   32          // scan chunks  (L = SMAX/NCH = 128)

// ---------------- scratch (device globals: no allocation allowed) ----------
__device__ float g_x   [(size_t)BMAX*SMAX*DMAX];        // normed input
__device__ float g_hg  [(size_t)BMAX*SMAX*2*DMAX];      // GEMM1 output [hidden|gate]
__device__ float g_c   [(size_t)BMAX*SMAX*DMAX];        // recurrence coeff
__device__ float g_v   [(size_t)BMAX*SMAX*DMAX];        // recurrence value
__device__ float g_h   [(size_t)BMAX*SMAX*DMAX];        // recurrence output
__device__ float g_Wi  [(size_t)BMAX*DMAX*2*DMAX];
__device__ float g_Wo  [(size_t)BMAX*DMAX*DMAX];
__device__ float g_part[(size_t)PPART*BMAX*DMAX];
__device__ float g_xmean[(size_t)BMAX*DMAX];
__device__ float g_probs[(size_t)BMAX*EMAX];
__device__ float g_Ach [(size_t)BMAX*NCH*DMAX];
__device__ float g_Ych [(size_t)BMAX*NCH*DMAX];
__device__ float g_hin [(size_t)BMAX*NCH*DMAX];

// ---------------- RMSNorm: one block per (b,s) row ------------------------
__global__ void rmsnorm_kernel(const float* __restrict__ inp,
                               const float* __restrict__ w, int D)
{
    long row = blockIdx.x;
    const float4* in4 = (const float4*)(inp + row*(long)D);
    float4*       xo4 = (float4*)(g_x + row*(long)D);
    const float4* w4  = (const float4*)w;

    int tid = threadIdx.x;
    int n4  = D >> 2;
    float ss = 0.f;
    for (int i = tid; i < n4; i += blockDim.x) {
        float4 t = in4[i];
        ss += t.x*t.x + t.y*t.y + t.z*t.z + t.w*t.w;
    }
    // block reduce
    for (int o = 16; o > 0; o >>= 1) ss += __shfl_xor_sync(0xffffffffu, ss, o);
    __shared__ float red[8];
    int warp = tid >> 5, lane = tid & 31;
    if (lane == 0) red[warp] = ss;
    __syncthreads();
    int nwarp = blockDim.x >> 5;
    __shared__ float s_r;
    if (tid == 0) {
        float tot = 0.f;
        for (int i = 0; i < nwarp; i++) tot += red[i];
        s_r = rsqrtf(tot / (float)D + 1e-6f);
    }
    __syncthreads();
    float r = s_r;
    for (int i = tid; i < n4; i += blockDim.x) {
        float4 t = in4[i];
        float4 ww = w4[i];
        float4 o;
        o.x = t.x * r * ww.x; o.y = t.y * r * ww.y;
        o.z = t.z * r * ww.z; o.w = t.w * r * ww.w;
        xo4[i] = o;
    }
}

// ---------------- column mean over S (two stage, deterministic) -----------
__global__ void colsum_partial_kernel(int B, int S, int D)
{
    int g = blockIdx.x * blockDim.x + threadIdx.x;
    int total = PPART * B * D;
    if (g >= total) return;
    int d = g % D;
    int b = (g / D) % B;
    int p = g / (D * B);
    int chunk = S / PPART;
    long base = ((long)b * S + (long)p * chunk) * D + d;
    float s = 0.f;
    for (int i = 0; i < chunk; i++) s += g_x[base + (long)i * D];
    g_part[g] = s;
}

__global__ void colsum_final_kernel(int B, int S, int D)
{
    int g = blockIdx.x * blockDim.x + threadIdx.x;
    if (g >= B * D) return;
    int d = g % D, b = g / D;
    float s = 0.f;
    for (int p = 0; p < PPART; p++) s += g_part[(p * B + b) * D + d];
    g_xmean[g] = s / (float)S;
}

// ---------------- router: logits + softmax (tiny, one block) --------------
__global__ void router_kernel(const float* __restrict__ rw, int B, int D, int E)
{
    __shared__ float sred[256];
    __shared__ float slog[BMAX * EMAX];
    int tid = threadIdx.x;
    for (int be = 0; be < B * E; be++) {
        int b = be / E, e = be % E;
        float s = 0.f;
        for (int d = tid; d < D; d += blockDim.x)
            s += g_xmean[b * D + d] * rw[(long)d * E + e];
        sred[tid] = s;
        __syncthreads();
        for (int o = 128; o > 0; o >>= 1) {
            if (tid < o) sred[tid] += sred[tid + o];
            __syncthreads();
        }
        if (tid == 0) slog[be] = sred[0];
        __syncthreads();
    }
    if (tid < B) {
        int b = tid;
        float m = -1e30f;
        for (int e = 0; e < E; e++) m = fmaxf(m, slog[b * E + e]);
        float sum = 0.f, p[EMAX];
        for (int e = 0; e < E; e++) { p[e] = expf(slog[b * E + e] - m); sum += p[e]; }
        float inv = 1.f / sum;
        for (int e = 0; e < E; e++) g_probs[b * E + e] = p[e] * inv;
    }
}

// ---------------- expert mixing: Wi/Wo = probs @ w ------------------------
__global__ void combine_kernel(const float* __restrict__ w,
                               float* __restrict__ dst,
                               int B, int E, long per /* floats per batch */)
{
    __shared__ float sp[BMAX * EMAX];
    if (threadIdx.x < B * E) sp[threadIdx.x] = g_probs[threadIdx.x];
    __syncthreads();
    long per4 = per >> 2;
    long g = (long)blockIdx.x * blockDim.x + threadIdx.x;
    long tot = (long)B * per4;
    if (g >= tot) return;
    int  b = (int)(g / per4);
    long r = g % per4;
    float4 acc = {0.f, 0.f, 0.f, 0.f};
    const float4* w4 = (const float4*)w;
#pragma unroll
    for (int e = 0; e < EMAX; e++) {
        float p = sp[b * E + e];
        float4 t = w4[(long)e * per4 + r];
        acc.x = fmaf(p, t.x, acc.x); acc.y = fmaf(p, t.y, acc.y);
        acc.z = fmaf(p, t.z, acc.z); acc.w = fmaf(p, t.w, acc.w);
    }
    ((float4*)dst)[g] = acc;
}

// ---------------- SGEMM: C[b] = A[b] @ B[b] (+ resid) ---------------------
// 128x128 tile, BK=8, 256 threads, 8x8 per-thread micro-tile.
__global__ __launch_bounds__(256)
void sgemm_kernel(const float* __restrict__ A, const float* __restrict__ Bm,
                  const float* __restrict__ resid, float* __restrict__ C,
                  int M, int N, int K,
                  long strideA, long strideB, long strideC)
{
    const int BK = 8;
    __shared__ __align__(16) float As[BK][128];
    __shared__ __align__(16) float Bs[BK][128];

    int b = blockIdx.z;
    A += (long)b * strideA;
    Bm += (long)b * strideB;
    C += (long)b * strideC;
    if (resid) resid += (long)b * strideC;

    long tileM = (long)blockIdx.y * 128;
    long tileN = (long)blockIdx.x * 128;
    int tid = threadIdx.x;

    int aRow = tid >> 1;            // 0..127
    int aCol = (tid & 1) << 2;      // 0 or 4
    int bRow = tid >> 5;            // 0..7
    int bCol = (tid & 31) << 2;     // 0..124

    int tr = (tid >> 4) << 3;       // 0..120 step 8
    int tc = (tid & 15) << 3;

    float acc[8][8];
#pragma unroll
    for (int i = 0; i < 8; i++)
#pragma unroll
        for (int j = 0; j < 8; j++) acc[i][j] = 0.f;

    for (int k0 = 0; k0 < K; k0 += BK) {
        float4 av = *(const float4*)(A + (tileM + aRow) * K + k0 + aCol);
        As[aCol + 0][aRow] = av.x;
        As[aCol + 1][aRow] = av.y;
        As[aCol + 2][aRow] = av.z;
        As[aCol + 3][aRow] = av.w;
        float4 bv = *(const float4*)(Bm + (long)(k0 + bRow) * N + tileN + bCol);
        *(float4*)(&Bs[bRow][bCol]) = bv;
        __syncthreads();
#pragma unroll
        for (int kk = 0; kk < BK; kk++) {
            float4 ra0 = *(const float4*)(&As[kk][tr]);
            float4 ra1 = *(const float4*)(&As[kk][tr + 4]);
            float4 rb0 = *(const float4*)(&Bs[kk][tc]);
            float4 rb1 = *(const float4*)(&Bs[kk][tc + 4]);
            float ra[8] = {ra0.x, ra0.y, ra0.z, ra0.w, ra1.x, ra1.y, ra1.z, ra1.w};
            float rb[8] = {rb0.x, rb0.y, rb0.z, rb0.w, rb1.x, rb1.y, rb1.z, rb1.w};
#pragma unroll
            for (int i = 0; i < 8; i++)
#pragma unroll
                for (int j = 0; j < 8; j++)
                    acc[i][j] = fmaf(ra[i], rb[j], acc[i][j]);
        }
        __syncthreads();
    }

#pragma unroll
    for (int i = 0; i < 8; i++) {
        long row = tileM + tr + i;
#pragma unroll
        for (int j = 0; j < 8; j += 4) {
            long idx = row * N + tileN + tc + j;
            float4 r;
            r.x = acc[i][j]; r.y = acc[i][j + 1]; r.z = acc[i][j + 2]; r.w = acc[i][j + 3];
            if (resid) {
                float4 rv = *(const float4*)(resid + idx);
                r.x += rv.x; r.y += rv.y; r.z += rv.z; r.w += rv.w;
            }
            *(float4*)(C + idx) = r;
        }
    }
}

// ---------------- gating: c = sigmoid(-gate), v = sigmoid(gate)*g(hidden) --
__device__ __forceinline__ void cv_one(float hid, float gate, float& c, float& v)
{
    float cc = 1.f / (1.f + expf(gate));           // sigmoid(-gate)
    float sg = 1.f - cc;                           // sigmoid(gate)
    float gg = (hid >= 0.f) ? (hid + 0.5f) : (1.f / (1.f + expf(-hid)));
    c = cc;
    v = sg * gg;
}

__global__ void cv_kernel(int B, int S, int D)
{
    long g = (long)blockIdx.x * blockDim.x + threadIdx.x;
    int n4 = D >> 2;
    long tot = (long)B * S * n4;
    if (g >= tot) return;
    int d4 = (int)(g % n4);
    long row = g / n4;   // b*S+s
    const float4* hrow = (const float4*)(g_hg + row * (2L * D));
    float4 hd = hrow[d4];
    float4 gt = hrow[n4 + d4];
    float4 c, v;
    cv_one(hd.x, gt.x, c.x, v.x);
    cv_one(hd.y, gt.y, c.y, v.y);
    cv_one(hd.z, gt.z, c.z, v.z);
    cv_one(hd.w, gt.w, c.w, v.w);
    ((float4*)(g_c + row * (long)D))[d4] = c;
    ((float4*)(g_v + row * (long)D))[d4] = v;
}

// ---------------- chunked linear-recurrence scan ---------------------------
__global__ void scan_passA_kernel(int B, int S, int D, int L, int nch)
{
    int g = blockIdx.x * blockDim.x + threadIdx.x;
    int total = B * nch * D;
    if (g >= total) return;
    int d = g % D;
    int ch = (g / D) % nch;
    int b = g / (D * nch);
    long base = ((long)b * S + (long)ch * L) * D + d;
    float A = 1.f, Y = 0.f;
    for (int i = 0; i < L; i++) {
        float c = g_c[base + (long)i * D];
        float v = g_v[base + (long)i * D];
        A *= c;
        Y = fmaf(c, Y, v);
    }
    g_Ach[g] = A;
    g_Ych[g] = Y;
}

__global__ void scan_passB_kernel(const float* __restrict__ state,
                                  float* __restrict__ out,
                                  int B, int D, int nch,
                                  long outBase, long out_size)
{
    int g = blockIdx.x * blockDim.x + threadIdx.x;
    if (g >= B * D) return;
    int d = g % D, b = g / D;
    float h = state[b * D + d];
    for (int ch = 0; ch < nch; ch++) {
        int idx = (b * nch + ch) * D + d;
        g_hin[idx] = h;
        h = fmaf(g_Ach[idx], h, g_Ych[idx]);
    }
    if (out_size >= outBase + (long)B * D)
        out[outBase + (long)b * D + d] = h;          // new_state
    if (g == 0 && out_size >= outBase + (long)B * D + 1)
        out[outBase + (long)B * D] = 0.f;            // aux_loss
}

__global__ void scan_passC_kernel(int B, int S, int D, int L, int nch)
{
    int g = blockIdx.x * blockDim.x + threadIdx.x;
    int total = B * nch * D;
    if (g >= total) return;
    int d = g % D;
    int ch = (g / D) % nch;
    int b = g / (D * nch);
    long base = ((long)b * S + (long)ch * L) * D + d;
    float h = g_hin[g];
    for (int i = 0; i < L; i++) {
        float c = g_c[base + (long)i * D];
        float v = g_v[base + (long)i * D];
        h = fmaf(c, h, v);
        g_h[base + (long)i * D] = h;
    }
}

// ---------------- launch ----------------------------------------------------
extern "C" void kernel_launch(void* const* d_in, const int* in_sizes, int n_in,
                              void* d_out, int out_size)
{
    const float* inputs   = (const float*)d_in[0];
    // d_in[1]: attention_mask (unused by reference)
    const float* state    = (const float*)d_in[2];
    const float* normw    = (const float*)d_in[3];
    const float* router_w = (const float*)d_in[4];
    const float* w_in     = (const float*)d_in[5];
    const float* w_out    = (const float*)d_in[6];
    float* out = (float*)d_out;

    const int D = in_sizes[3];
    const int E = in_sizes[4] / D;
    const int B = in_sizes[2] / D;
    const int S = in_sizes[0] / (B * D);
    const int N2 = 2 * D;
    const int L = S / NCH;

    float *px, *phg, *ph, *pWi, *pWo;
    cudaGetSymbolAddress((void**)&px,  g_x);
    cudaGetSymbolAddress((void**)&phg, g_hg);
    cudaGetSymbolAddress((void**)&ph,  g_h);
    cudaGetSymbolAddress((void**)&pWi, g_Wi);
    cudaGetSymbolAddress((void**)&pWo, g_Wo);

    // 1. RMSNorm
    rmsnorm_kernel<<<B * S, 256>>>(inputs, normw, D);

    // 2. column mean (for router)
    {
        int total = PPART * B * D;
        colsum_partial_kernel<<<(total + 255) / 256, 256>>>(B, S, D);
        colsum_final_kernel<<<(B * D + 255) / 256, 256>>>(B, S, D);
    }

    // 3. router softmax
    router_kernel<<<1, 256>>>(router_w, B, D, E);

    // 4. expert-mixed weights
    {
        long perI = (long)D * N2;
        long totI = (long)B * (perI >> 2);
        combine_kernel<<<(int)((totI + 255) / 256), 256>>>(w_in, pWi, B, E, perI);
        long perO = (long)D * D;
        long totO = (long)B * (perO >> 2);
        combine_kernel<<<(int)((totO + 255) / 256), 256>>>(w_out, pWo, B, E, perO);
    }

    // 5. GEMM1: hg = x @ Wi   (M=S, N=2D, K=D)
    {
        dim3 grid(N2 / 128, S / 128, B);
        sgemm_kernel<<<grid, 256>>>(px, pWi, nullptr, phg,
                                    S, N2, D,
                                    (long)S * D, (long)D * N2, (long)S * N2);
    }

    // 6. gating elementwise
    {
        long tot = (long)B * S * (D >> 2);
        cv_kernel<<<(int)((tot + 255) / 256), 256>>>(B, S, D);
    }

    // 7. chunked scan
    {
        int totA = B * NCH * D;
        scan_passA_kernel<<<(totA + 255) / 256, 256>>>(B, S, D, L, NCH);
        scan_passB_kernel<<<(B * D + 255) / 256, 256>>>(state, out, B, D, NCH,
                                                        (long)B * S * D, (long)out_size);
        scan_passC_kernel<<<(totA + 255) / 256, 256>>>(B, S, D, L, NCH);
    }

    // 8. GEMM2: out = h @ Wo + inputs   (M=S, N=D, K=D)
    {
        dim3 grid(D / 128, S / 128, B);
        sgemm_kernel<<<grid, 256>>>(ph, pWo, inputs, out,
                                    S, D, D,
                                    (long)S * D, (long)D * D, (long)S * D);
    }
}

// round 2
// speedup vs baseline: 3.1023x; 3.1023x over previous
#include <cuda_runtime.h>
#include <math.h>
#include <stdint.h>

// Problem constants (dataset shapes)
#define BMAX 4
#define SMAX 4096
#define DMAX 1024
#define EMAX 8
#define PPART 32          // partial-sum parts for column mean
#define NCH   32          // scan chunks  (L = SMAX/NCH = 128)

// ---------------- scratch (device globals: no allocation allowed) ----------
__device__ float g_x   [(size_t)BMAX*SMAX*DMAX];        // normed input
__device__ float g_hg  [(size_t)BMAX*SMAX*2*DMAX];      // GEMM1 output [hidden|gate]
__device__ float g_c   [(size_t)BMAX*SMAX*DMAX];        // recurrence coeff
__device__ float g_v   [(size_t)BMAX*SMAX*DMAX];        // recurrence value
__device__ float g_h   [(size_t)BMAX*SMAX*DMAX];        // recurrence output
__device__ float g_Wi  [(size_t)BMAX*DMAX*2*DMAX];
__device__ float g_Wo  [(size_t)BMAX*DMAX*DMAX];
__device__ float g_part[(size_t)PPART*BMAX*DMAX];
__device__ float g_xmean[(size_t)BMAX*DMAX];
__device__ float g_probs[(size_t)BMAX*EMAX];
__device__ float g_Ach [(size_t)BMAX*NCH*DMAX];
__device__ float g_Ych [(size_t)BMAX*NCH*DMAX];
__device__ float g_hin [(size_t)BMAX*NCH*DMAX];

// ---------------- helpers ---------------------------------------------------
__device__ __forceinline__ uint32_t f2tf32(float x) {
    uint32_t y;
    asm("cvt.rna.tf32.f32 %0, %1;" : "=r"(y) : "f"(x));
    return y;
}
__device__ __forceinline__ float rcp_fast(float x) {
    float r;
    asm("rcp.approx.ftz.f32 %0, %1;" : "=f"(r) : "f"(x));
    return r;
}

// ---------------- RMSNorm: one block per (b,s) row ------------------------
__global__ void rmsnorm_kernel(const float* __restrict__ inp,
                               const float* __restrict__ w, int D)
{
    long row = blockIdx.x;
    const float4* in4 = (const float4*)(inp + row*(long)D);
    float4*       xo4 = (float4*)(g_x + row*(long)D);
    const float4* w4  = (const float4*)w;

    int tid = threadIdx.x;
    int n4  = D >> 2;
    float ss = 0.f;
    for (int i = tid; i < n4; i += blockDim.x) {
        float4 t = in4[i];
        ss += t.x*t.x + t.y*t.y + t.z*t.z + t.w*t.w;
    }
    for (int o = 16; o > 0; o >>= 1) ss += __shfl_xor_sync(0xffffffffu, ss, o);
    __shared__ float red[8];
    int warp = tid >> 5, lane = tid & 31;
    if (lane == 0) red[warp] = ss;
    __syncthreads();
    int nwarp = blockDim.x >> 5;
    __shared__ float s_r;
    if (tid == 0) {
        float tot = 0.f;
        for (int i = 0; i < nwarp; i++) tot += red[i];
        s_r = rsqrtf(tot / (float)D + 1e-6f);
    }
    __syncthreads();
    float r = s_r;
    for (int i = tid; i < n4; i += blockDim.x) {
        float4 t = in4[i];
        float4 ww = w4[i];
        float4 o;
        o.x = t.x * r * ww.x; o.y = t.y * r * ww.y;
        o.z = t.z * r * ww.z; o.w = t.w * r * ww.w;
        xo4[i] = o;
    }
}

// ---------------- column mean over S (two stage, deterministic) -----------
__global__ void colsum_partial_kernel(int B, int S, int D)
{
    int g = blockIdx.x * blockDim.x + threadIdx.x;
    int total = PPART * B * D;
    if (g >= total) return;
    int d = g % D;
    int b = (g / D) % B;
    int p = g / (D * B);
    int chunk = S / PPART;
    long base = ((long)b * S + (long)p * chunk) * D + d;
    float s = 0.f;
    for (int i = 0; i < chunk; i++) s += g_x[base + (long)i * D];
    g_part[g] = s;
}

__global__ void colsum_final_kernel(int B, int S, int D)
{
    int g = blockIdx.x * blockDim.x + threadIdx.x;
    if (g >= B * D) return;
    int d = g % D, b = g / D;
    float s = 0.f;
    for (int p = 0; p < PPART; p++) s += g_part[(p * B + b) * D + d];
    g_xmean[g] = s / (float)S;
}

// ---------------- router: warp per (b,e) logit + softmax -------------------
__global__ void router_kernel(const float* __restrict__ rw, int B, int D, int E)
{
    __shared__ float slog[BMAX * EMAX];
    int w = threadIdx.x >> 5, lane = threadIdx.x & 31;
    if (w < B * E) {
        int b = w / E, e = w % E;
        float s = 0.f;
        for (int d = lane; d < D; d += 32)
            s += g_xmean[b * D + d] * rw[(long)d * E + e];
        for (int o = 16; o > 0; o >>= 1) s += __shfl_xor_sync(0xffffffffu, s, o);
        if (lane == 0) slog[w] = s;
    }
    __syncthreads();
    if (threadIdx.x < (unsigned)B) {
        int b = threadIdx.x;
        float m = -1e30f;
        for (int e = 0; e < E; e++) m = fmaxf(m, slog[b * E + e]);
        float sum = 0.f, p[EMAX];
        for (int e = 0; e < E; e++) { p[e] = expf(slog[b * E + e] - m); sum += p[e]; }
        float inv = 1.f / sum;
        for (int e = 0; e < E; e++) g_probs[b * E + e] = p[e] * inv;
    }
}

// ---------------- expert mixing: Wi/Wo = probs @ w ------------------------
__global__ void combine_kernel(const float* __restrict__ w,
                               float* __restrict__ dst,
                               int B, int E, long per /* floats per batch */)
{
    __shared__ float sp[BMAX * EMAX];
    if (threadIdx.x < B * E) sp[threadIdx.x] = g_probs[threadIdx.x];
    __syncthreads();
    long per4 = per >> 2;
    long g = (long)blockIdx.x * blockDim.x + threadIdx.x;
    long tot = (long)B * per4;
    if (g >= tot) return;
    int  b = (int)(g / per4);
    long r = g % per4;
    float4 acc = {0.f, 0.f, 0.f, 0.f};
    const float4* w4 = (const float4*)w;
#pragma unroll
    for (int e = 0; e < EMAX; e++) {
        float p = sp[b * E + e];
        float4 t = w4[(long)e * per4 + r];
        acc.x = fmaf(p, t.x, acc.x); acc.y = fmaf(p, t.y, acc.y);
        acc.z = fmaf(p, t.z, acc.z); acc.w = fmaf(p, t.w, acc.w);
    }
    ((float4*)dst)[g] = acc;
}

// ---------------- TF32 tensor-core GEMM: C[b] = A[b] @ B[b] (+resid) -------
// 128x128 tile, BK=32, 256 threads (8 warps, 2x4), warp tile 64x32,
// mma.sync.m16n8k8.tf32, register-staged global prefetch.
#define BM 128
#define BN 128
#define BKK 32
#define APAD 8
#define BPAD 8

__global__ __launch_bounds__(256)
void tf32_gemm_kernel(const float* __restrict__ A, const float* __restrict__ Bm,
                      const float* __restrict__ resid, float* __restrict__ C,
                      int M, int N, int K,
                      long strideA, long strideB, long strideC)
{
    __shared__ uint32_t As[BKK][BM + APAD];   // [k][m]
    __shared__ uint32_t Bs[BKK][BN + BPAD];   // [k][n]

    int bz = blockIdx.z;
    A += (long)bz * strideA;
    Bm += (long)bz * strideB;
    C += (long)bz * strideC;
    if (resid) resid += (long)bz * strideC;

    const long tileM = (long)blockIdx.y * BM;
    const long tileN = (long)blockIdx.x * BN;
    const int tid = threadIdx.x;
    const int warp = tid >> 5;
    const int lane = tid & 31;
    const int wm = (warp >> 2) * 64;     // warp M offset (0,64)
    const int wn = (warp & 3) * 32;      // warp N offset (0..96)
    const int grp = lane >> 2;           // 0..7
    const int tig = lane & 3;            // 0..3

    float acc[4][4][4];
#pragma unroll
    for (int i = 0; i < 4; i++)
#pragma unroll
        for (int j = 0; j < 4; j++)
#pragma unroll
            for (int r = 0; r < 4; r++) acc[i][j][r] = 0.f;

    float4 aReg[4], bReg[4];

    // ---- prologue: load + store chunk 0 ----
#pragma unroll
    for (int j = 0; j < 4; j++) {
        int f4 = j * 256 + tid;
        int ar = f4 >> 3, aq = f4 & 7;
        aReg[j] = *(const float4*)(A + (tileM + ar) * K + aq * 4);
        int br = f4 >> 5, bc = f4 & 31;
        bReg[j] = *(const float4*)(Bm + (long)br * N + tileN + bc * 4);
    }
#pragma unroll
    for (int j = 0; j < 4; j++) {
        int f4 = j * 256 + tid;
        int ar = f4 >> 3, aq = f4 & 7;
        As[aq * 4 + 0][ar] = f2tf32(aReg[j].x);
        As[aq * 4 + 1][ar] = f2tf32(aReg[j].y);
        As[aq * 4 + 2][ar] = f2tf32(aReg[j].z);
        As[aq * 4 + 3][ar] = f2tf32(aReg[j].w);
        int br = f4 >> 5, bc = f4 & 31;
        uint4 bv;
        bv.x = f2tf32(bReg[j].x); bv.y = f2tf32(bReg[j].y);
        bv.z = f2tf32(bReg[j].z); bv.w = f2tf32(bReg[j].w);
        *(uint4*)(&Bs[br][bc * 4]) = bv;
    }
    __syncthreads();

    for (int k0 = BKK; k0 <= K; k0 += BKK) {
        // prefetch next chunk into registers
        if (k0 < K) {
#pragma unroll
            for (int j = 0; j < 4; j++) {
                int f4 = j * 256 + tid;
                int ar = f4 >> 3, aq = f4 & 7;
                aReg[j] = *(const float4*)(A + (tileM + ar) * K + k0 + aq * 4);
                int br = f4 >> 5, bc = f4 & 31;
                bReg[j] = *(const float4*)(Bm + (long)(k0 + br) * N + tileN + bc * 4);
            }
        }
        // compute on current smem chunk
#pragma unroll
        for (int ks = 0; ks < 4; ks++) {
            const int kb = ks * 8;
            uint32_t af[4][4], bf[4][2];
#pragma unroll
            for (int mf = 0; mf < 4; mf++) {
                int m = wm + mf * 16 + grp;
                af[mf][0] = As[kb + tig][m];
                af[mf][1] = As[kb + tig][m + 8];
                af[mf][2] = As[kb + tig + 4][m];
                af[mf][3] = As[kb + tig + 4][m + 8];
            }
#pragma unroll
            for (int nf = 0; nf < 4; nf++) {
                int n = wn + nf * 8 + grp;
                bf[nf][0] = Bs[kb + tig][n];
                bf[nf][1] = Bs[kb + tig + 4][n];
            }
#pragma unroll
            for (int mf = 0; mf < 4; mf++)
#pragma unroll
                for (int nf = 0; nf < 4; nf++) {
                    asm volatile(
                        "mma.sync.aligned.m16n8k8.row.col.f32.tf32.tf32.f32 "
                        "{%0,%1,%2,%3},{%4,%5,%6,%7},{%8,%9},{%0,%1,%2,%3};"
                        : "+f"(acc[mf][nf][0]), "+f"(acc[mf][nf][1]),
                          "+f"(acc[mf][nf][2]), "+f"(acc[mf][nf][3])
                        : "r"(af[mf][0]), "r"(af[mf][1]), "r"(af[mf][2]), "r"(af[mf][3]),
                          "r"(bf[nf][0]), "r"(bf[nf][1]));
                }
        }
        if (k0 < K) {
            __syncthreads();
#pragma unroll
            for (int j = 0; j < 4; j++) {
                int f4 = j * 256 + tid;
                int ar = f4 >> 3, aq = f4 & 7;
                As[aq * 4 + 0][ar] = f2tf32(aReg[j].x);
                As[aq * 4 + 1][ar] = f2tf32(aReg[j].y);
                As[aq * 4 + 2][ar] = f2tf32(aReg[j].z);
                As[aq * 4 + 3][ar] = f2tf32(aReg[j].w);
                int br = f4 >> 5, bc = f4 & 31;
                uint4 bv;
                bv.x = f2tf32(bReg[j].x); bv.y = f2tf32(bReg[j].y);
                bv.z = f2tf32(bReg[j].z); bv.w = f2tf32(bReg[j].w);
                *(uint4*)(&Bs[br][bc * 4]) = bv;
            }
            __syncthreads();
        }
    }

    // ---- epilogue ----
#pragma unroll
    for (int mf = 0; mf < 4; mf++) {
#pragma unroll
        for (int nf = 0; nf < 4; nf++) {
            long row0 = tileM + wm + mf * 16 + grp;
            long col  = tileN + wn + nf * 8 + 2 * tig;
            long i0 = row0 * N + col;
            long i1 = (row0 + 8) * N + col;
            float2 r0 = make_float2(acc[mf][nf][0], acc[mf][nf][1]);
            float2 r1 = make_float2(acc[mf][nf][2], acc[mf][nf][3]);
            if (resid) {
                float2 q0 = *(const float2*)(resid + i0);
                float2 q1 = *(const float2*)(resid + i1);
                r0.x += q0.x; r0.y += q0.y;
                r1.x += q1.x; r1.y += q1.y;
            }
            *(float2*)(C + i0) = r0;
            *(float2*)(C + i1) = r1;
        }
    }
}

// ---------------- gating + chunk-scan pass A (fused) -----------------------
__device__ __forceinline__ void cv_one(float hid, float gate, float& c, float& v)
{
    float t = __expf(-fabsf(gate));
    float r = rcp_fast(1.f + t);
    float sg, cc;
    if (gate >= 0.f) { sg = r;      cc = t * r; }
    else             { sg = t * r;  cc = r;     }
    float gg;
    if (hid >= 0.f) gg = hid + 0.5f;
    else {
        float t2 = __expf(hid);
        gg = t2 * rcp_fast(1.f + t2);
    }
    c = cc;
    v = sg * gg;
}

__global__ void cva_kernel(int B, int S, int D, int L, int nch)
{
    int g = blockIdx.x * blockDim.x + threadIdx.x;
    int total = B * nch * D;
    if (g >= total) return;
    int d = g % D;
    int ch = (g / D) % nch;
    int b = g / (D * nch);
    long rowbase = (long)b * S + (long)ch * L;
    const float* hgp = g_hg + rowbase * (2L * D) + d;
    float* cp = g_c + rowbase * (long)D + d;
    float* vp = g_v + rowbase * (long)D + d;
    float A = 1.f, Y = 0.f;
    for (int i = 0; i < L; i++) {
        float hd = hgp[(long)i * 2 * D];
        float gt = hgp[(long)i * 2 * D + D];
        float c, v;
        cv_one(hd, gt, c, v);
        cp[(long)i * D] = c;
        vp[(long)i * D] = v;
        A *= c;
        Y = fmaf(c, Y, v);
    }
    g_Ach[g] = A;
    g_Ych[g] = Y;
}

__global__ void scan_passB_kernel(const float* __restrict__ state,
                                  float* __restrict__ out,
                                  int B, int D, int nch,
                                  long outBase, long out_size)
{
    int g = blockIdx.x * blockDim.x + threadIdx.x;
    if (g >= B * D) return;
    int d = g % D, b = g / D;
    float h = state[b * D + d];
    for (int ch = 0; ch < nch; ch++) {
        int idx = (b * nch + ch) * D + d;
        g_hin[idx] = h;
        h = fmaf(g_Ach[idx], h, g_Ych[idx]);
    }
    if (out_size >= outBase + (long)B * D)
        out[outBase + (long)b * D + d] = h;          // new_state
    if (g == 0 && out_size >= outBase + (long)B * D + 1)
        out[outBase + (long)B * D] = 0.f;            // aux_loss
}

__global__ void scan_passC_kernel(int B, int S, int D, int L, int nch)
{
    int g = blockIdx.x * blockDim.x + threadIdx.x;
    int total = B * nch * D;
    if (g >= total) return;
    int d = g % D;
    int ch = (g / D) % nch;
    int b = g / (D * nch);
    long base = ((long)b * S + (long)ch * L) * D + d;
    float h = g_hin[g];
    for (int i = 0; i < L; i++) {
        float c = g_c[base + (long)i * D];
        float v = g_v[base + (long)i * D];
        h = fmaf(c, h, v);
        g_h[base + (long)i * D] = h;
    }
}

// ---------------- launch ----------------------------------------------------
extern "C" void kernel_launch(void* const* d_in, const int* in_sizes, int n_in,
                              void* d_out, int out_size)
{
    const float* inputs   = (const float*)d_in[0];
    // d_in[1]: attention_mask (unused by reference)
    const float* state    = (const float*)d_in[2];
    const float* normw    = (const float*)d_in[3];
    const float* router_w = (const float*)d_in[4];
    const float* w_in     = (const float*)d_in[5];
    const float* w_out    = (const float*)d_in[6];
    float* out = (float*)d_out;

    const int D = in_sizes[3];
    const int E = in_sizes[4] / D;
    const int B = in_sizes[2] / D;
    const int S = in_sizes[0] / (B * D);
    const int N2 = 2 * D;
    const int L = S / NCH;

    float *px, *phg, *ph, *pWi, *pWo;
    cudaGetSymbolAddress((void**)&px,  g_x);
    cudaGetSymbolAddress((void**)&phg, g_hg);
    cudaGetSymbolAddress((void**)&ph,  g_h);
    cudaGetSymbolAddress((void**)&pWi, g_Wi);
    cudaGetSymbolAddress((void**)&pWo, g_Wo);

    // 1. RMSNorm
    rmsnorm_kernel<<<B * S, 256>>>(inputs, normw, D);

    // 2. column mean (for router)
    {
        int total = PPART * B * D;
        colsum_partial_kernel<<<(total + 255) / 256, 256>>>(B, S, D);
        colsum_final_kernel<<<(B * D + 255) / 256, 256>>>(B, S, D);
    }

    // 3. router softmax (warp per (b,e))
    router_kernel<<<1, 1024>>>(router_w, B, D, E);

    // 4. expert-mixed weights
    {
        long perI = (long)D * N2;
        long totI = (long)B * (perI >> 2);
        combine_kernel<<<(int)((totI + 255) / 256), 256>>>(w_in, pWi, B, E, perI);
        long perO = (long)D * D;
        long totO = (long)B * (perO >> 2);
        combine_kernel<<<(int)((totO + 255) / 256), 256>>>(w_out, pWo, B, E, perO);
    }

    // 5. GEMM1: hg = x @ Wi   (M=S, N=2D, K=D)  -- tf32 tensor cores
    {
        dim3 grid(N2 / BN, S / BM, B);
        tf32_gemm_kernel<<<grid, 256>>>(px, pWi, nullptr, phg,
                                        S, N2, D,
                                        (long)S * D, (long)D * N2, (long)S * N2);
    }

    // 6. gating + scan pass A (fused)
    {
        int totA = B * NCH * D;
        cva_kernel<<<(totA + 255) / 256, 256>>>(B, S, D, L, NCH);
        scan_passB_kernel<<<(B * D + 255) / 256, 256>>>(state, out, B, D, NCH,
                                                        (long)B * S * D, (long)out_size);
        scan_passC_kernel<<<(totA + 255) / 256, 256>>>(B, S, D, L, NCH);
    }

    // 7. GEMM2: out = h @ Wo + inputs   (M=S, N=D, K=D) -- tf32 tensor cores
    {
        dim3 grid(D / BN, S / BM, B);
        tf32_gemm_kernel<<<grid, 256>>>(ph, pWo, inputs, out,
                                        S, D, D,
                                        (long)S * D, (long)D * D, (long)S * D);
    }
}

// round 4
// speedup vs baseline: 5.1134x; 1.6483x over previous
#include <cuda_runtime.h>
#include <math.h>
#include <stdint.h>

// Problem constants (dataset shapes)
#define BMAX 4
#define SMAX 4096
#define DMAX 1024
#define EMAX 8
#define PPART 32          // partial-sum parts for column mean
#define NCH   32          // scan chunks  (L = SMAX/NCH = 128)

// ---------------- scratch (device globals: no allocation allowed) ----------
__device__ float g_x   [(size_t)BMAX*SMAX*DMAX];        // normed input (tf32-rounded)
__device__ float g_hg  [(size_t)BMAX*SMAX*2*DMAX];      // reused: (c,v) float2 pairs
__device__ float g_h   [(size_t)BMAX*SMAX*DMAX];        // recurrence output (tf32-rounded)
__device__ float g_Wi  [(size_t)BMAX*DMAX*2*DMAX];      // Wi^T  [B][2D][D] K-major, interleaved cols
__device__ float g_Wo  [(size_t)BMAX*DMAX*DMAX];        // Wo^T  [B][D][D]  K-major
__device__ float g_part[(size_t)PPART*BMAX*DMAX];
__device__ float g_probs[(size_t)BMAX*EMAX];
__device__ float g_Ach [(size_t)BMAX*NCH*DMAX];
__device__ float g_Ych [(size_t)BMAX*NCH*DMAX];
__device__ float g_hin [(size_t)BMAX*NCH*DMAX];

// ---------------- helpers ---------------------------------------------------
__device__ __forceinline__ uint32_t f2tf32(float x) {
    uint32_t y;
    asm("cvt.rna.tf32.f32 %0, %1;" : "=r"(y) : "f"(x));
    return y;
}
__device__ __forceinline__ float tf32r(float x) { return __uint_as_float(f2tf32(x)); }
__device__ __forceinline__ float rcp_fast(float x) {
    float r;
    asm("rcp.approx.ftz.f32 %0, %1;" : "=f"(r) : "f"(x));
    return r;
}
__device__ __forceinline__ uint32_t smem_u32(const void* p) {
    uint32_t a;
    asm("{ .reg .u64 t; cvta.to.shared.u64 t, %1; cvt.u32.u64 %0, t; }"
        : "=r"(a) : "l"(p));
    return a;
}
__device__ __forceinline__ void cp16(uint32_t dst, const void* src) {
    asm volatile("cp.async.cg.shared.global [%0], [%1], 16;"
                 :: "r"(dst), "l"(src) : "memory");
}
__device__ __forceinline__ uint32_t lds32(uint32_t a) {
    uint32_t v;
    asm volatile("ld.shared.b32 %0, [%1];" : "=r"(v) : "r"(a));
    return v;
}

// ---------------- RMSNorm: one block per (b,s) row ------------------------
__global__ void rmsnorm_kernel(const float* __restrict__ inp,
                               const float* __restrict__ w, int D)
{
    long row = blockIdx.x;
    const float4* in4 = (const float4*)(inp + row*(long)D);
    float4*       xo4 = (float4*)(g_x + row*(long)D);
    const float4* w4  = (const float4*)w;

    int tid = threadIdx.x;
    int n4  = D >> 2;
    float ss = 0.f;
    for (int i = tid; i < n4; i += blockDim.x) {
        float4 t = in4[i];
        ss += t.x*t.x + t.y*t.y + t.z*t.z + t.w*t.w;
    }
    for (int o = 16; o > 0; o >>= 1) ss += __shfl_xor_sync(0xffffffffu, ss, o);
    __shared__ float red[8];
    int warp = tid >> 5, lane = tid & 31;
    if (lane == 0) red[warp] = ss;
    __syncthreads();
    int nwarp = blockDim.x >> 5;
    __shared__ float s_r;
    if (tid == 0) {
        float tot = 0.f;
        for (int i = 0; i < nwarp; i++) tot += red[i];
        s_r = rsqrtf(tot / (float)D + 1e-6f);
    }
    __syncthreads();
    float r = s_r;
    for (int i = tid; i < n4; i += blockDim.x) {
        float4 t = in4[i];
        float4 ww = w4[i];
        float4 o;
        o.x = tf32r(t.x * r * ww.x); o.y = tf32r(t.y * r * ww.y);
        o.z = tf32r(t.z * r * ww.z); o.w = tf32r(t.w * r * ww.w);
        xo4[i] = o;
    }
}

// ---------------- column mean over S, stage 1 ------------------------------
__global__ void colsum_partial_kernel(int B, int S, int D)
{
    int g = blockIdx.x * blockDim.x + threadIdx.x;
    int total = PPART * B * D;
    if (g >= total) return;
    int d = g % D;
    int b = (g / D) % B;
    int p = g / (D * B);
    int chunk = S / PPART;
    long base = ((long)b * S + (long)p * chunk) * D + d;
    float s = 0.f;
    for (int i = 0; i < chunk; i++) s += g_x[base + (long)i * D];
    g_part[g] = s;
}

// ------- fused: colsum finalize + router logits + softmax (1 block) --------
__global__ void router_fused_kernel(const float* __restrict__ rw,
                                    int B, int S, int D, int E)
{
    __shared__ float sxm[BMAX * DMAX];      // 16 KB
    __shared__ float slog[BMAX * EMAX];
    int tid = threadIdx.x;                  // 1024 threads
    for (int i = tid; i < B * D; i += blockDim.x) {
        float s = 0.f;
        for (int p = 0; p < PPART; p++) s += g_part[p * B * D + i];
        sxm[i] = s / (float)S;
    }
    __syncthreads();
    int w = tid >> 5, lane = tid & 31;
    if (w < B * E) {
        int b = w / E, e = w % E;
        float s = 0.f;
        for (int d = lane; d < D; d += 32)
            s += sxm[b * D + d] * rw[(long)d * E + e];
        for (int o = 16; o > 0; o >>= 1) s += __shfl_xor_sync(0xffffffffu, s, o);
        if (lane == 0) slog[w] = s;
    }
    __syncthreads();
    if (tid < (unsigned)B) {
        int b = tid;
        float m = -1e30f;
        for (int e = 0; e < E; e++) m = fmaxf(m, slog[b * E + e]);
        float sum = 0.f, p[EMAX];
        for (int e = 0; e < E; e++) { p[e] = expf(slog[b * E + e] - m); sum += p[e]; }
        float inv = 1.f / sum;
        for (int e = 0; e < E; e++) g_probs[b * E + e] = p[e] * inv;
    }
}

// ------- expert mixing with transpose: dst[b][n'][k] = sum_e p*w[e][k][n] ---
// w: [E][Dk][Dn] (n contiguous). dst: [B][Dn][Dk] (k contiguous, tf32-rounded).
// interleave!=0: output row n -> 2*(n%Dh) + n/Dh   (pairs hidden/gate columns)
__global__ void combineT_kernel(const float* __restrict__ w,
                                float* __restrict__ dst,
                                int E, int Dk, int Dn, int interleave, int Dh)
{
    __shared__ float ts[32][33];
    __shared__ float sp[EMAX];
    int b = blockIdx.z;
    if (threadIdx.x < (unsigned)E) sp[threadIdx.x] = g_probs[b * E + threadIdx.x];
    __syncthreads();
    int k0 = blockIdx.x * 32, n0 = blockIdx.y * 32;
    {
        int tk = threadIdx.x >> 3;        // 0..31
        int tn4 = threadIdx.x & 7;        // 0..7
        float4 acc = {0.f, 0.f, 0.f, 0.f};
        const float* base = w + (long)(k0 + tk) * Dn + n0 + tn4 * 4;
        long estride = (long)Dk * Dn;
#pragma unroll
        for (int e = 0; e < EMAX; e++) {
            float p = sp[e];
            float4 t = *(const float4*)(base + e * estride);
            acc.x = fmaf(p, t.x, acc.x); acc.y = fmaf(p, t.y, acc.y);
            acc.z = fmaf(p, t.z, acc.z); acc.w = fmaf(p, t.w, acc.w);
        }
        ts[tk][tn4 * 4 + 0] = acc.x;
        ts[tk][tn4 * 4 + 1] = acc.y;
        ts[tk][tn4 * 4 + 2] = acc.z;
        ts[tk][tn4 * 4 + 3] = acc.w;
    }
    __syncthreads();
    {
        int tn = threadIdx.x >> 3;
        int tk4 = threadIdx.x & 7;
        int nrow = n0 + tn;
        if (interleave) nrow = 2 * (nrow % Dh) + (nrow / Dh);
        float4 o;
        o.x = tf32r(ts[tk4 * 4 + 0][tn]);
        o.y = tf32r(ts[tk4 * 4 + 1][tn]);
        o.z = tf32r(ts[tk4 * 4 + 2][tn]);
        o.w = tf32r(ts[tk4 * 4 + 3][tn]);
        *(float4*)(dst + ((long)b * Dn + nrow) * Dk + k0 + tk4 * 4) = o;
    }
}

// ---------------- gating scalar ---------------------------------------------
__device__ __forceinline__ void cv_one(float hid, float gate, float& c, float& v)
{
    float t = __expf(-fabsf(gate));
    float r = rcp_fast(1.f + t);
    float sg, cc;
    if (gate >= 0.f) { sg = r;      cc = t * r; }
    else             { sg = t * r;  cc = r;     }
    float gg;
    if (hid >= 0.f) gg = hid + 0.5f;
    else {
        float t2 = __expf(hid);
        gg = t2 * rcp_fast(1.f + t2);
    }
    c = cc;
    v = sg * gg;
}

// ---------------- tf32 mma.sync GEMM, cp.async 3-stage ----------------------
// A: [M][K] K-major (tf32-rounded fp32).  Bt: [N][K] K-major (tf32-rounded).
// CTA tile 128x256, 8 warps (2x4) of 64x64. BK=32.
// MODE 0: Cout = A@Bt^T + resid      (resid may be null)
// MODE 1: treat output cols as (hidden,gate) pairs; write (c,v) float2 to cv.
#define STAGES 3
#define CTA_M 128
#define CTA_N 256
#define GBK 32
#define A_BYTES (CTA_M * GBK * 4)                 // 16384
#define B_BYTES (CTA_N * GBK * 4)                 // 32768
#define STAGE_BYTES (A_BYTES + B_BYTES)           // 49152
#define GEMM_SMEM (STAGES * STAGE_BYTES + 1024)

template<int MODE>
__global__ void __launch_bounds__(256, 1)
tc_gemm(const float* __restrict__ A, const float* __restrict__ Bt,
        const float* __restrict__ resid, float* __restrict__ Cout,
        float2* __restrict__ cv,
        int M, int N, int K, long sA, long sB, long sC, int Dh, int S)
{
    extern __shared__ char dsm[];
    const uint32_t sb = (smem_u32(dsm) + 1023u) & ~1023u;

    const int bz = blockIdx.z;
    A  += (long)bz * sA;
    Bt += (long)bz * sB;

    const long tileM = (long)blockIdx.y * CTA_M;
    const long tileN = (long)blockIdx.x * CTA_N;
    const int tid  = threadIdx.x;
    const int warp = tid >> 5;
    const int lane = tid & 31;
    const int wm = (warp >> 2) * 64;   // 0,64
    const int wn = (warp & 3) * 64;    // 0..192
    const int grp = lane >> 2;         // 0..7
    const int tig = lane & 3;          // 0..3

    float acc[4][8][4];
#pragma unroll
    for (int i = 0; i < 4; i++)
#pragma unroll
        for (int j = 0; j < 8; j++)
#pragma unroll
            for (int r = 0; r < 4; r++) acc[i][j][r] = 0.f;

    auto fill_stage = [&](int stage, int ch) {
        uint32_t bAf = sb + stage * STAGE_BYTES;
        uint32_t bBf = bAf + A_BYTES;
        int k0 = ch * GBK;
#pragma unroll
        for (int j = 0; j < 4; j++) {
            int idx = j * 256 + tid;
            int row = idx >> 3, seg = idx & 7;
            uint32_t off = (uint32_t)(row * 128) + (uint32_t)((seg * 16) ^ ((row & 7) * 16));
            cp16(bAf + off, A + (tileM + row) * K + k0 + seg * 4);
        }
#pragma unroll
        for (int j = 0; j < 8; j++) {
            int idx = j * 256 + tid;
            int row = idx >> 3, seg = idx & 7;
            uint32_t off = (uint32_t)(row * 128) + (uint32_t)((seg * 16) ^ ((row & 7) * 16));
            cp16(bBf + off, Bt + (tileN + row) * K + k0 + seg * 4);
        }
        asm volatile("cp.async.commit_group;" ::: "memory");
    };

    const int nch = K / GBK;
    fill_stage(0, 0);
    fill_stage(1, 1);

    for (int ch = 0; ch < nch; ch++) {
        int st = ch % STAGES;
        asm volatile("cp.async.wait_group %0;" :: "n"(STAGES - 2) : "memory");
        __syncthreads();
        if (ch + 2 < nch) fill_stage((ch + 2) % STAGES, ch + 2);
        else asm volatile("cp.async.commit_group;" ::: "memory");

        uint32_t bA = sb + st * STAGE_BYTES;
        uint32_t bB = bA + A_BYTES;
        uint32_t aRB0[4], aRB1[4], aMK[4];
#pragma unroll
        for (int mf = 0; mf < 4; mf++) {
            int m0 = wm + mf * 16 + grp;
            aRB0[mf] = bA + m0 * 128;
            aRB1[mf] = bA + (m0 + 8) * 128;
            aMK[mf] = (uint32_t)((m0 & 7) * 16);
        }
        uint32_t bRB[8], bMK[8];
#pragma unroll
        for (int nf = 0; nf < 8; nf++) {
            int n0 = wn + nf * 8 + grp;
            bRB[nf] = bB + n0 * 128;
            bMK[nf] = (uint32_t)((n0 & 7) * 16);
        }
#pragma unroll
        for (int ks = 0; ks < 4; ks++) {
            uint32_t k4a = (uint32_t)((ks * 8 + tig) * 4);
            uint32_t k4b = k4a + 16;
            uint32_t af[4][4];
#pragma unroll
            for (int mf = 0; mf < 4; mf++) {
                af[mf][0] = lds32(aRB0[mf] + (k4a ^ aMK[mf]));
                af[mf][1] = lds32(aRB1[mf] + (k4a ^ aMK[mf]));
                af[mf][2] = lds32(aRB0[mf] + (k4b ^ aMK[mf]));
                af[mf][3] = lds32(aRB1[mf] + (k4b ^ aMK[mf]));
            }
            uint32_t bf[8][2];
#pragma unroll
            for (int nf = 0; nf < 8; nf++) {
                bf[nf][0] = lds32(bRB[nf] + (k4a ^ bMK[nf]));
                bf[nf][1] = lds32(bRB[nf] + (k4b ^ bMK[nf]));
            }
#pragma unroll
            for (int mf = 0; mf < 4; mf++)
#pragma unroll
                for (int nf = 0; nf < 8; nf++) {
                    asm volatile(
                        "mma.sync.aligned.m16n8k8.row.col.f32.tf32.tf32.f32 "
                        "{%0,%1,%2,%3},{%4,%5,%6,%7},{%8,%9},{%0,%1,%2,%3};"
                        : "+f"(acc[mf][nf][0]), "+f"(acc[mf][nf][1]),
                          "+f"(acc[mf][nf][2]), "+f"(acc[mf][nf][3])
                        : "r"(af[mf][0]), "r"(af[mf][1]), "r"(af[mf][2]), "r"(af[mf][3]),
                          "r"(bf[nf][0]), "r"(bf[nf][1]));
                }
        }
    }

    // ---- epilogue ----
    if (MODE == 0) {
        const float* rz = resid ? resid + (long)bz * sC : nullptr;
        float* cz = Cout + (long)bz * sC;
#pragma unroll
        for (int mf = 0; mf < 4; mf++) {
#pragma unroll
            for (int nf = 0; nf < 8; nf++) {
                long r0 = tileM + wm + mf * 16 + grp;
                long c  = tileN + wn + nf * 8 + 2 * tig;
                long i0 = r0 * N + c;
                long i1 = (r0 + 8) * N + c;
                float2 v0 = make_float2(acc[mf][nf][0], acc[mf][nf][1]);
                float2 v1 = make_float2(acc[mf][nf][2], acc[mf][nf][3]);
                if (rz) {
                    float2 q0 = *(const float2*)(rz + i0);
                    float2 q1 = *(const float2*)(rz + i1);
                    v0.x += q0.x; v0.y += q0.y;
                    v1.x += q1.x; v1.y += q1.y;
                }
                *(float2*)(cz + i0) = v0;
                *(float2*)(cz + i1) = v1;
            }
        }
    } else {
        float2* cvb = cv + (long)bz * S * (long)Dh;
#pragma unroll
        for (int mf = 0; mf < 4; mf++) {
#pragma unroll
            for (int nf = 0; nf < 8; nf++) {
                long r0 = tileM + wm + mf * 16 + grp;
                long c  = tileN + wn + nf * 8 + 2 * tig;
                long d  = c >> 1;
                float cc, vv;
                cv_one(acc[mf][nf][0], acc[mf][nf][1], cc, vv);
                cvb[r0 * Dh + d] = make_float2(cc, vv);
                cv_one(acc[mf][nf][2], acc[mf][nf][3], cc, vv);
                cvb[(r0 + 8) * Dh + d] = make_float2(cc, vv);
            }
        }
    }
}

// ---------------- chunked linear-recurrence scan ---------------------------
__global__ void scan_passA_kernel(int B, int S, int D, int L, int nch)
{
    int g = blockIdx.x * blockDim.x + threadIdx.x;
    int total = B * nch * D;
    if (g >= total) return;
    int d = g % D;
    int ch = (g / D) % nch;
    int b = g / (D * nch);
    const float2* cv = (const float2*)g_hg;
    long base = ((long)b * S + (long)ch * L) * D + d;
    float A = 1.f, Y = 0.f;
    for (int i = 0; i < L; i++) {
        float2 t = cv[base + (long)i * D];
        A *= t.x;
        Y = fmaf(t.x, Y, t.y);
    }
    g_Ach[g] = A;
    g_Ych[g] = Y;
}

__global__ void scan_passB_kernel(const float* __restrict__ state,
                                  float* __restrict__ out,
                                  int B, int D, int nch,
                                  long outBase, long out_size)
{
    int g = blockIdx.x * blockDim.x + threadIdx.x;
    if (g >= B * D) return;
    int d = g % D, b = g / D;
    float h = state[b * D + d];
    for (int ch = 0; ch < nch; ch++) {
        int idx = (b * nch + ch) * D + d;
        g_hin[idx] = h;
        h = fmaf(g_Ach[idx], h, g_Ych[idx]);
    }
    if (out_size >= outBase + (long)B * D)
        out[outBase + (long)b * D + d] = h;          // new_state
    if (g == 0 && out_size >= outBase + (long)B * D + 1)
        out[outBase + (long)B * D] = 0.f;            // aux_loss
}

__global__ void scan_passC_kernel(int B, int S, int D, int L, int nch)
{
    int g = blockIdx.x * blockDim.x + threadIdx.x;
    int total = B * nch * D;
    if (g >= total) return;
    int d = g % D;
    int ch = (g / D) % nch;
    int b = g / (D * nch);
    const float2* cv = (const float2*)g_hg;
    long base = ((long)b * S + (long)ch * L) * D + d;
    float h = g_hin[g];
    for (int i = 0; i < L; i++) {
        float2 t = cv[base + (long)i * D];
        h = fmaf(t.x, h, t.y);
        g_h[base + (long)i * D] = tf32r(h);
    }
}

// ---------------- launch ----------------------------------------------------
extern "C" void kernel_launch(void* const* d_in, const int* in_sizes, int n_in,
                              void* d_out, int out_size)
{
    const float* inputs   = (const float*)d_in[0];
    // d_in[1]: attention_mask (unused by reference)
    const float* state    = (const float*)d_in[2];
    const float* normw    = (const float*)d_in[3];
    const float* router_w = (const float*)d_in[4];
    const float* w_in     = (const float*)d_in[5];
    const float* w_out    = (const float*)d_in[6];
    float* out = (float*)d_out;

    const int D = in_sizes[3];
    const int E = in_sizes[4] / D;
    const int B = in_sizes[2] / D;
    const int S = in_sizes[0] / (B * D);
    const int N2 = 2 * D;
    const int L = S / NCH;

    float *px, *phg, *ph, *pWi, *pWo;
    cudaGetSymbolAddress((void**)&px,  g_x);
    cudaGetSymbolAddress((void**)&phg, g_hg);
    cudaGetSymbolAddress((void**)&ph,  g_h);
    cudaGetSymbolAddress((void**)&pWi, g_Wi);
    cudaGetSymbolAddress((void**)&pWo, g_Wo);

    cudaFuncSetAttribute(tc_gemm<0>, cudaFuncAttributeMaxDynamicSharedMemorySize, GEMM_SMEM);
    cudaFuncSetAttribute(tc_gemm<1>, cudaFuncAttributeMaxDynamicSharedMemorySize, GEMM_SMEM);

    // 1. RMSNorm (tf32-rounded output)
    rmsnorm_kernel<<<B * S, 256>>>(inputs, normw, D);

    // 2. column partial sums
    {
        int total = PPART * B * D;
        colsum_partial_kernel<<<(total + 255) / 256, 256>>>(B, S, D);
    }

    // 3. fused colsum-final + router softmax
    router_fused_kernel<<<1, 1024>>>(router_w, B, S, D, E);

    // 4. expert-mixed transposed weights (tf32-rounded)
    {
        dim3 gI(D / 32, N2 / 32, B);
        combineT_kernel<<<gI, 256>>>(w_in, pWi, E, D, N2, 1, D);   // interleaved
        dim3 gO(D / 32, D / 32, B);
        combineT_kernel<<<gO, 256>>>(w_out, pWo, E, D, D, 0, D);
    }

    // 5. GEMM1 (M=S, N=2D, K=D) with fused gating -> (c,v) pairs in g_hg
    {
        dim3 grid(N2 / CTA_N, S / CTA_M, B);
        tc_gemm<1><<<grid, 256, GEMM_SMEM>>>(px, pWi, nullptr, nullptr,
                                             (float2*)phg,
                                             S, N2, D,
                                             (long)S * D, (long)N2 * D, 0L,
                                             D, S);
    }

    // 6. chunked scan
    {
        int totA = B * NCH * D;
        scan_passA_kernel<<<(totA + 255) / 256, 256>>>(B, S, D, L, NCH);
        scan_passB_kernel<<<(B * D + 255) / 256, 256>>>(state, out, B, D, NCH,
                                                        (long)B * S * D, (long)out_size);
        scan_passC_kernel<<<(totA + 255) / 256, 256>>>(B, S, D, L, NCH);
    }

    // 7. GEMM2: out = h @ Wo^T + inputs   (M=S, N=D, K=D)
    {
        dim3 grid(D / CTA_N, S / CTA_M, B);
        tc_gemm<0><<<grid, 256, GEMM_SMEM>>>(ph, pWo, inputs, out,
                                             nullptr,
                                             S, D, D,
                                             (long)S * D, (long)D * D, (long)S * D,
                                             D, S);
    }
}

// round 5
// speedup vs baseline: 7.6237x; 1.4909x over previous
#include <cuda_runtime.h>
#include <cuda_fp16.h>
#include <math.h>
#include <stdint.h>

// Problem constants (dataset shapes)
#define BMAX 4
#define SMAX 4096
#define DMAX 1024
#define EMAX 8
#define PPART 32          // partial-sum parts for column mean
#define NCH   32          // scan chunks  (L = SMAX/NCH = 128)

// ---------------- scratch (device globals: no allocation allowed) ----------
__device__ __half g_x  [(size_t)BMAX*SMAX*DMAX];        // normed input (fp16)
__device__ float  g_hg [(size_t)BMAX*SMAX*2*DMAX];      // (c,v) float2 pairs
__device__ __half g_h  [(size_t)BMAX*SMAX*DMAX];        // recurrence output (fp16)
__device__ __half g_Wi [(size_t)BMAX*DMAX*2*DMAX];      // Wi^T [B][2D][D] K-major, interleaved
__device__ __half g_Wo [(size_t)BMAX*DMAX*DMAX];        // Wo^T [B][D][D]  K-major
__device__ float  g_part[(size_t)PPART*BMAX*DMAX];
__device__ float  g_probs[(size_t)BMAX*EMAX];
__device__ float  g_Ach [(size_t)BMAX*NCH*DMAX];
__device__ float  g_Ych [(size_t)BMAX*NCH*DMAX];
__device__ float  g_hin [(size_t)BMAX*NCH*DMAX];

// ---------------- helpers ---------------------------------------------------
__device__ __forceinline__ float rcp_fast(float x) {
    float r;
    asm("rcp.approx.ftz.f32 %0, %1;" : "=f"(r) : "f"(x));
    return r;
}
__device__ __forceinline__ uint32_t smem_u32(const void* p) {
    uint32_t a;
    asm("{ .reg .u64 t; cvta.to.shared.u64 t, %1; cvt.u32.u64 %0, t; }"
        : "=r"(a) : "l"(p));
    return a;
}
__device__ __forceinline__ void cp16(uint32_t dst, const void* src) {
    asm volatile("cp.async.cg.shared.global [%0], [%1], 16;"
                 :: "r"(dst), "l"(src) : "memory");
}
__device__ __forceinline__ uint32_t lds32(uint32_t a) {
    uint32_t v;
    asm volatile("ld.shared.b32 %0, [%1];" : "=r"(v) : "r"(a));
    return v;
}

// ---------------- RMSNorm: one block per (b,s) row, fp16 out ---------------
__global__ void rmsnorm_kernel(const float* __restrict__ inp,
                               const float* __restrict__ w, int D)
{
    long row = blockIdx.x;
    const float4* in4 = (const float4*)(inp + row*(long)D);
    __half2* xo2 = (__half2*)(g_x + row*(long)D);
    const float4* w4  = (const float4*)w;

    int tid = threadIdx.x;
    int n4  = D >> 2;
    float ss = 0.f;
    for (int i = tid; i < n4; i += blockDim.x) {
        float4 t = in4[i];
        ss += t.x*t.x + t.y*t.y + t.z*t.z + t.w*t.w;
    }
    for (int o = 16; o > 0; o >>= 1) ss += __shfl_xor_sync(0xffffffffu, ss, o);
    __shared__ float red[8];
    int warp = tid >> 5, lane = tid & 31;
    if (lane == 0) red[warp] = ss;
    __syncthreads();
    int nwarp = blockDim.x >> 5;
    __shared__ float s_r;
    if (tid == 0) {
        float tot = 0.f;
        for (int i = 0; i < nwarp; i++) tot += red[i];
        s_r = rsqrtf(tot / (float)D + 1e-6f);
    }
    __syncthreads();
    float r = s_r;
    for (int i = tid; i < n4; i += blockDim.x) {
        float4 t = in4[i];
        float4 ww = w4[i];
        xo2[i*2 + 0] = __floats2half2_rn(t.x * r * ww.x, t.y * r * ww.y);
        xo2[i*2 + 1] = __floats2half2_rn(t.z * r * ww.z, t.w * r * ww.w);
    }
}

// ---------------- column mean over S, stage 1 (reads fp16 x) ---------------
__global__ void colsum_partial_kernel(int B, int S, int D)
{
    int g = blockIdx.x * blockDim.x + threadIdx.x;
    int total = PPART * B * D;
    if (g >= total) return;
    int d = g % D;
    int b = (g / D) % B;
    int p = g / (D * B);
    int chunk = S / PPART;
    long base = ((long)b * S + (long)p * chunk) * D + d;
    float s = 0.f;
    for (int i = 0; i < chunk; i++) s += __half2float(g_x[base + (long)i * D]);
    g_part[g] = s;
}

// ------- fused: colsum finalize + router logits + softmax (1 block) --------
__global__ void router_fused_kernel(const float* __restrict__ rw,
                                    int B, int S, int D, int E)
{
    __shared__ float sxm[BMAX * DMAX];      // 16 KB
    __shared__ float slog[BMAX * EMAX];
    int tid = threadIdx.x;                  // 1024 threads
    for (int i = tid; i < B * D; i += blockDim.x) {
        float s = 0.f;
        for (int p = 0; p < PPART; p++) s += g_part[p * B * D + i];
        sxm[i] = s / (float)S;
    }
    __syncthreads();
    int w = tid >> 5, lane = tid & 31;
    if (w < B * E) {
        int b = w / E, e = w % E;
        float s = 0.f;
        for (int d = lane; d < D; d += 32)
            s += sxm[b * D + d] * rw[(long)d * E + e];
        for (int o = 16; o > 0; o >>= 1) s += __shfl_xor_sync(0xffffffffu, s, o);
        if (lane == 0) slog[w] = s;
    }
    __syncthreads();
    if (tid < (unsigned)B) {
        int b = tid;
        float m = -1e30f;
        for (int e = 0; e < E; e++) m = fmaxf(m, slog[b * E + e]);
        float sum = 0.f, p[EMAX];
        for (int e = 0; e < E; e++) { p[e] = expf(slog[b * E + e] - m); sum += p[e]; }
        float inv = 1.f / sum;
        for (int e = 0; e < E; e++) g_probs[b * E + e] = p[e] * inv;
    }
}

// ------- expert mixing + transpose, all batches per tile load --------------
// w: [E][Dk][Dn] (n contiguous). dst: [B][Dn][Dk] (k contiguous, fp16).
// interleave!=0: output row n -> 2*(n%Dh) + n/Dh   (pairs hidden/gate cols)
__global__ void combineT_kernel(const float* __restrict__ w,
                                __half* __restrict__ dst,
                                int B, int E, int Dk, int Dn,
                                int interleave, int Dh)
{
    __shared__ float ts[32][33];
    __shared__ float sp[BMAX * EMAX];
    if (threadIdx.x < (unsigned)(B * E)) sp[threadIdx.x] = g_probs[threadIdx.x];
    __syncthreads();
    int k0 = blockIdx.x * 32, n0 = blockIdx.y * 32;
    int tk = threadIdx.x >> 3;        // 0..31
    int tn4 = threadIdx.x & 7;        // 0..7
    int tn = tk, tk4 = tn4;           // roles for write phase

    float4 t[EMAX];
    {
        const float* base = w + (long)(k0 + tk) * Dn + n0 + tn4 * 4;
        long estride = (long)Dk * Dn;
#pragma unroll
        for (int e = 0; e < EMAX; e++)
            t[e] = *(const float4*)(base + e * estride);
    }
    for (int b = 0; b < B; b++) {
        float4 acc = {0.f, 0.f, 0.f, 0.f};
#pragma unroll
        for (int e = 0; e < EMAX; e++) {
            float p = sp[b * EMAX + e];
            acc.x = fmaf(p, t[e].x, acc.x); acc.y = fmaf(p, t[e].y, acc.y);
            acc.z = fmaf(p, t[e].z, acc.z); acc.w = fmaf(p, t[e].w, acc.w);
        }
        ts[tk][tn4 * 4 + 0] = acc.x;
        ts[tk][tn4 * 4 + 1] = acc.y;
        ts[tk][tn4 * 4 + 2] = acc.z;
        ts[tk][tn4 * 4 + 3] = acc.w;
        __syncthreads();
        int nrow = n0 + tn;
        if (interleave) nrow = 2 * (nrow % Dh) + (nrow / Dh);
        __half2 h01 = __floats2half2_rn(ts[tk4 * 4 + 0][tn], ts[tk4 * 4 + 1][tn]);
        __half2 h23 = __floats2half2_rn(ts[tk4 * 4 + 2][tn], ts[tk4 * 4 + 3][tn]);
        __half2* dp = (__half2*)(dst + ((long)b * Dn + nrow) * Dk + k0 + tk4 * 4);
        dp[0] = h01;
        dp[1] = h23;
        __syncthreads();
    }
}

// ---------------- gating scalar ---------------------------------------------
__device__ __forceinline__ void cv_one(float hid, float gate, float& c, float& v)
{
    float t = __expf(-fabsf(gate));
    float r = rcp_fast(1.f + t);
    float sg, cc;
    if (gate >= 0.f) { sg = r;      cc = t * r; }
    else             { sg = t * r;  cc = r;     }
    float gg;
    if (hid >= 0.f) gg = hid + 0.5f;
    else {
        float t2 = __expf(hid);
        gg = t2 * rcp_fast(1.f + t2);
    }
    c = cc;
    v = sg * gg;
}

// ---------------- fp16 mma.sync GEMM, cp.async 3-stage ----------------------
// A: [M][K] K-major fp16.  Bt: [N][K] K-major fp16.  fp32 accumulate.
// CTA tile 128x256, 8 warps (2x4) of 64x64. BK=64 (rows = 128 bytes).
// MODE 0: Cout = A@Bt^T + resid (fp32).  MODE 1: (hidden,gate)->(c,v) pairs.
#define STAGES 3
#define CTA_M 128
#define CTA_N 256
#define GBK 64
#define A_BYTES (CTA_M * GBK * 2)                 // 16384
#define B_BYTES (CTA_N * GBK * 2)                 // 32768
#define STAGE_BYTES (A_BYTES + B_BYTES)           // 49152
#define GEMM_SMEM (STAGES * STAGE_BYTES + 1024)

template<int MODE>
__global__ void __launch_bounds__(256, 1)
tc_gemm(const __half* __restrict__ A, const __half* __restrict__ Bt,
        const float* __restrict__ resid, float* __restrict__ Cout,
        float2* __restrict__ cv,
        int M, int N, int K, long sA, long sB, long sC, int Dh, int S)
{
    extern __shared__ char dsm[];
    const uint32_t sb = (smem_u32(dsm) + 1023u) & ~1023u;

    const int bz = blockIdx.z;
    A  += (long)bz * sA;
    Bt += (long)bz * sB;

    const long tileM = (long)blockIdx.y * CTA_M;
    const long tileN = (long)blockIdx.x * CTA_N;
    const int tid  = threadIdx.x;
    const int warp = tid >> 5;
    const int lane = tid & 31;
    const int wm = (warp >> 2) * 64;   // 0,64
    const int wn = (warp & 3) * 64;    // 0..192
    const int grp = lane >> 2;         // 0..7
    const int tig = lane & 3;          // 0..3

    float acc[4][8][4];
#pragma unroll
    for (int i = 0; i < 4; i++)
#pragma unroll
        for (int j = 0; j < 8; j++)
#pragma unroll
            for (int r = 0; r < 4; r++) acc[i][j][r] = 0.f;

    auto fill_stage = [&](int stage, int ch) {
        uint32_t bAf = sb + stage * STAGE_BYTES;
        uint32_t bBf = bAf + A_BYTES;
        int k0 = ch * GBK;
#pragma unroll
        for (int j = 0; j < 4; j++) {
            int idx = j * 256 + tid;
            int row = idx >> 3, seg = idx & 7;
            uint32_t off = (uint32_t)(row * 128) + (uint32_t)((seg * 16) ^ ((row & 7) * 16));
            cp16(bAf + off, A + (tileM + row) * K + k0 + seg * 8);
        }
#pragma unroll
        for (int j = 0; j < 8; j++) {
            int idx = j * 256 + tid;
            int row = idx >> 3, seg = idx & 7;
            uint32_t off = (uint32_t)(row * 128) + (uint32_t)((seg * 16) ^ ((row & 7) * 16));
            cp16(bBf + off, Bt + (tileN + row) * K + k0 + seg * 8);
        }
        asm volatile("cp.async.commit_group;" ::: "memory");
    };

    const int nch = K / GBK;
    fill_stage(0, 0);
    fill_stage(1, 1);

    for (int ch = 0; ch < nch; ch++) {
        int st = ch % STAGES;
        asm volatile("cp.async.wait_group %0;" :: "n"(STAGES - 2) : "memory");
        __syncthreads();
        if (ch + 2 < nch) fill_stage((ch + 2) % STAGES, ch + 2);
        else asm volatile("cp.async.commit_group;" ::: "memory");

        uint32_t bA = sb + st * STAGE_BYTES;
        uint32_t bB = bA + A_BYTES;
        uint32_t aRB0[4], aRB1[4], aMK[4];
#pragma unroll
        for (int mf = 0; mf < 4; mf++) {
            int m0 = wm + mf * 16 + grp;
            aRB0[mf] = bA + m0 * 128;
            aRB1[mf] = bA + (m0 + 8) * 128;
            aMK[mf] = (uint32_t)((m0 & 7) * 16);
        }
        uint32_t bRB[8], bMK[8];
#pragma unroll
        for (int nf = 0; nf < 8; nf++) {
            int n0 = wn + nf * 8 + grp;
            bRB[nf] = bB + n0 * 128;
            bMK[nf] = (uint32_t)((n0 & 7) * 16);
        }
#pragma unroll
        for (int ks = 0; ks < 4; ks++) {
            uint32_t klo = (uint32_t)(ks * 32 + tig * 4);
            uint32_t khi = klo + 16;
            uint32_t af[4][4];
#pragma unroll
            for (int mf = 0; mf < 4; mf++) {
                af[mf][0] = lds32(aRB0[mf] + (klo ^ aMK[mf]));
                af[mf][1] = lds32(aRB1[mf] + (klo ^ aMK[mf]));
                af[mf][2] = lds32(aRB0[mf] + (khi ^ aMK[mf]));
                af[mf][3] = lds32(aRB1[mf] + (khi ^ aMK[mf]));
            }
            uint32_t bf[8][2];
#pragma unroll
            for (int nf = 0; nf < 8; nf++) {
                bf[nf][0] = lds32(bRB[nf] + (klo ^ bMK[nf]));
                bf[nf][1] = lds32(bRB[nf] + (khi ^ bMK[nf]));
            }
#pragma unroll
            for (int mf = 0; mf < 4; mf++)
#pragma unroll
                for (int nf = 0; nf < 8; nf++) {
                    asm volatile(
                        "mma.sync.aligned.m16n8k16.row.col.f32.f16.f16.f32 "
                        "{%0,%1,%2,%3},{%4,%5,%6,%7},{%8,%9},{%0,%1,%2,%3};"
                        : "+f"(acc[mf][nf][0]), "+f"(acc[mf][nf][1]),
                          "+f"(acc[mf][nf][2]), "+f"(acc[mf][nf][3])
                        : "r"(af[mf][0]), "r"(af[mf][1]), "r"(af[mf][2]), "r"(af[mf][3]),
                          "r"(bf[nf][0]), "r"(bf[nf][1]));
                }
        }
    }

    // ---- epilogue ----
    if (MODE == 0) {
        const float* rz = resid ? resid + (long)bz * sC : nullptr;
        float* czp = Cout + (long)bz * sC;
#pragma unroll
        for (int mf = 0; mf < 4; mf++) {
#pragma unroll
            for (int nf = 0; nf < 8; nf++) {
                long r0 = tileM + wm + mf * 16 + grp;
                long c  = tileN + wn + nf * 8 + 2 * tig;
                long i0 = r0 * N + c;
                long i1 = (r0 + 8) * N + c;
                float2 v0 = make_float2(acc[mf][nf][0], acc[mf][nf][1]);
                float2 v1 = make_float2(acc[mf][nf][2], acc[mf][nf][3]);
                if (rz) {
                    float2 q0 = *(const float2*)(rz + i0);
                    float2 q1 = *(const float2*)(rz + i1);
                    v0.x += q0.x; v0.y += q0.y;
                    v1.x += q1.x; v1.y += q1.y;
                }
                *(float2*)(czp + i0) = v0;
                *(float2*)(czp + i1) = v1;
            }
        }
    } else {
        float2* cvb = cv + (long)bz * S * (long)Dh;
#pragma unroll
        for (int mf = 0; mf < 4; mf++) {
#pragma unroll
            for (int nf = 0; nf < 8; nf++) {
                long r0 = tileM + wm + mf * 16 + grp;
                long c  = tileN + wn + nf * 8 + 2 * tig;
                long d  = c >> 1;
                float cc, vv;
                cv_one(acc[mf][nf][0], acc[mf][nf][1], cc, vv);
                cvb[r0 * Dh + d] = make_float2(cc, vv);
                cv_one(acc[mf][nf][2], acc[mf][nf][3], cc, vv);
                cvb[(r0 + 8) * Dh + d] = make_float2(cc, vv);
            }
        }
    }
}

// ---------------- chunked linear-recurrence scan ---------------------------
__global__ void scan_passA_kernel(int B, int S, int D, int L, int nch)
{
    int g = blockIdx.x * blockDim.x + threadIdx.x;
    int total = B * nch * D;
    if (g >= total) return;
    int d = g % D;
    int ch = (g / D) % nch;
    int b = g / (D * nch);
    const float2* cv = (const float2*)g_hg;
    long base = ((long)b * S + (long)ch * L) * D + d;
    float A = 1.f, Y = 0.f;
    for (int i = 0; i < L; i++) {
        float2 t = cv[base + (long)i * D];
        A *= t.x;
        Y = fmaf(t.x, Y, t.y);
    }
    g_Ach[g] = A;
    g_Ych[g] = Y;
}

__global__ void scan_passB_kernel(const float* __restrict__ state,
                                  float* __restrict__ out,
                                  int B, int D, int nch,
                                  long outBase, long out_size)
{
    int g = blockIdx.x * blockDim.x + threadIdx.x;
    if (g >= B * D) return;
    int d = g % D, b = g / D;
    float h = state[b * D + d];
    for (int ch = 0; ch < nch; ch++) {
        int idx = (b * nch + ch) * D + d;
        g_hin[idx] = h;
        h = fmaf(g_Ach[idx], h, g_Ych[idx]);
    }
    if (out_size >= outBase + (long)B * D)
        out[outBase + (long)b * D + d] = h;          // new_state
    if (g == 0 && out_size >= outBase + (long)B * D + 1)
        out[outBase + (long)B * D] = 0.f;            // aux_loss
}

__global__ void scan_passC_kernel(int B, int S, int D, int L, int nch)
{
    int g = blockIdx.x * blockDim.x + threadIdx.x;
    int total = B * nch * D;
    if (g >= total) return;
    int d = g % D;
    int ch = (g / D) % nch;
    int b = g / (D * nch);
    const float2* cv = (const float2*)g_hg;
    long base = ((long)b * S + (long)ch * L) * D + d;
    float h = g_hin[g];
    for (int i = 0; i < L; i++) {
        float2 t = cv[base + (long)i * D];
        h = fmaf(t.x, h, t.y);
        g_h[base + (long)i * D] = __float2half_rn(h);
    }
}

// ---------------- launch ----------------------------------------------------
extern "C" void kernel_launch(void* const* d_in, const int* in_sizes, int n_in,
                              void* d_out, int out_size)
{
    const float* inputs   = (const float*)d_in[0];
    // d_in[1]: attention_mask (unused by reference)
    const float* state    = (const float*)d_in[2];
    const float* normw    = (const float*)d_in[3];
    const float* router_w = (const float*)d_in[4];
    const float* w_in     = (const float*)d_in[5];
    const float* w_out    = (const float*)d_in[6];
    float* out = (float*)d_out;

    const int D = in_sizes[3];
    const int E = in_sizes[4] / D;
    const int B = in_sizes[2] / D;
    const int S = in_sizes[0] / (B * D);
    const int N2 = 2 * D;
    const int L = S / NCH;

    __half *px, *ph, *pWi, *pWo;
    float *phg;
    cudaGetSymbolAddress((void**)&px,  g_x);
    cudaGetSymbolAddress((void**)&phg, g_hg);
    cudaGetSymbolAddress((void**)&ph,  g_h);
    cudaGetSymbolAddress((void**)&pWi, g_Wi);
    cudaGetSymbolAddress((void**)&pWo, g_Wo);

    cudaFuncSetAttribute(tc_gemm<0>, cudaFuncAttributeMaxDynamicSharedMemorySize, GEMM_SMEM);
    cudaFuncSetAttribute(tc_gemm<1>, cudaFuncAttributeMaxDynamicSharedMemorySize, GEMM_SMEM);

    // 1. RMSNorm (fp16 output)
    rmsnorm_kernel<<<B * S, 256>>>(inputs, normw, D);

    // 2. column partial sums
    {
        int total = PPART * B * D;
        colsum_partial_kernel<<<(total + 255) / 256, 256>>>(B, S, D);
    }

    // 3. fused colsum-final + router softmax
    router_fused_kernel<<<1, 1024>>>(router_w, B, S, D, E);

    // 4. expert-mixed transposed weights (fp16, all batches per tile)
    {
        dim3 gI(D / 32, N2 / 32);
        combineT_kernel<<<gI, 256>>>(w_in, pWi, B, E, D, N2, 1, D);   // interleaved
        dim3 gO(D / 32, D / 32);
        combineT_kernel<<<gO, 256>>>(w_out, pWo, B, E, D, D, 0, D);
    }

    // 5. GEMM1 (M=S, N=2D, K=D) with fused gating -> (c,v) pairs in g_hg
    {
        dim3 grid(N2 / CTA_N, S / CTA_M, B);
        tc_gemm<1><<<grid, 256, GEMM_SMEM>>>(px, pWi, nullptr, nullptr,
                                             (float2*)phg,
                                             S, N2, D,
                                             (long)S * D, (long)N2 * D, 0L,
                                             D, S);
    }

    // 6. chunked scan
    {
        int totA = B * NCH * D;
        scan_passA_kernel<<<(totA + 255) / 256, 256>>>(B, S, D, L, NCH);
        scan_passB_kernel<<<(B * D + 255) / 256, 256>>>(state, out, B, D, NCH,
                                                        (long)B * S * D, (long)out_size);
        scan_passC_kernel<<<(totA + 255) / 256, 256>>>(B, S, D, L, NCH);
    }

    // 7. GEMM2: out = h @ Wo^T + inputs   (M=S, N=D, K=D)
    {
        dim3 grid(D / CTA_N, S / CTA_M, B);
        tc_gemm<0><<<grid, 256, GEMM_SMEM>>>(ph, pWo, inputs, out,
                                             nullptr,
                                             S, D, D,
                                             (long)S * D, (long)D * D, (long)S * D,
                                             D, S);
    }
}

// round 6
// speedup vs baseline: 8.1601x; 1.0704x over previous
#include <cuda_runtime.h>
#include <cuda_fp16.h>
#include <math.h>
#include <stdint.h>

// Problem constants (dataset shapes)
#define BMAX 4
#define SMAX 4096
#define DMAX 1024
#define EMAX 8
#define PPART 32          // partial-sum parts for column mean
#define NCH   32          // scan chunks  (L = SMAX/NCH = 128)

// ---------------- scratch (device globals: no allocation allowed) ----------
__device__ __half g_x  [(size_t)BMAX*SMAX*DMAX];        // normed input (fp16)
__device__ float  g_hg [(size_t)BMAX*SMAX*2*DMAX];      // (c,v) float2 pairs
__device__ __half g_h  [(size_t)BMAX*SMAX*DMAX];        // recurrence output (fp16)
__device__ __half g_Wi [(size_t)BMAX*DMAX*2*DMAX];      // Wi^T [B][2D][D] K-major, interleaved
__device__ __half g_Wo [(size_t)BMAX*DMAX*DMAX];        // Wo^T [B][D][D]  K-major
__device__ float  g_part[(size_t)PPART*BMAX*DMAX];
__device__ float  g_probs[(size_t)BMAX*EMAX];
__device__ float  g_Ach [(size_t)BMAX*NCH*DMAX];
__device__ float  g_Ych [(size_t)BMAX*NCH*DMAX];
__device__ float  g_hin [(size_t)BMAX*NCH*DMAX];

// ---------------- helpers ---------------------------------------------------
__device__ __forceinline__ float rcp_fast(float x) {
    float r;
    asm("rcp.approx.ftz.f32 %0, %1;" : "=f"(r) : "f"(x));
    return r;
}
__device__ __forceinline__ uint32_t smem_u32(const void* p) {
    uint32_t a;
    asm("{ .reg .u64 t; cvta.to.shared.u64 t, %1; cvt.u32.u64 %0, t; }"
        : "=r"(a) : "l"(p));
    return a;
}
__device__ __forceinline__ void cp16(uint32_t dst, const void* src) {
    asm volatile("cp.async.cg.shared.global [%0], [%1], 16;"
                 :: "r"(dst), "l"(src) : "memory");
}
__device__ __forceinline__ uint32_t lds32(uint32_t a) {
    uint32_t v;
    asm volatile("ld.shared.b32 %0, [%1];" : "=r"(v) : "r"(a));
    return v;
}

// ---------------- RMSNorm: one block per (b,s) row, fp16 out ---------------
__global__ void rmsnorm_kernel(const float* __restrict__ inp,
                               const float* __restrict__ w, int D)
{
    long row = blockIdx.x;
    const float4* in4 = (const float4*)(inp + row*(long)D);
    __half2* xo2 = (__half2*)(g_x + row*(long)D);
    const float4* w4  = (const float4*)w;

    int tid = threadIdx.x;
    int n4  = D >> 2;
    float ss = 0.f;
    for (int i = tid; i < n4; i += blockDim.x) {
        float4 t = in4[i];
        ss += t.x*t.x + t.y*t.y + t.z*t.z + t.w*t.w;
    }
    for (int o = 16; o > 0; o >>= 1) ss += __shfl_xor_sync(0xffffffffu, ss, o);
    __shared__ float red[8];
    int warp = tid >> 5, lane = tid & 31;
    if (lane == 0) red[warp] = ss;
    __syncthreads();
    int nwarp = blockDim.x >> 5;
    __shared__ float s_r;
    if (tid == 0) {
        float tot = 0.f;
        for (int i = 0; i < nwarp; i++) tot += red[i];
        s_r = rsqrtf(tot / (float)D + 1e-6f);
    }
    __syncthreads();
    float r = s_r;
    for (int i = tid; i < n4; i += blockDim.x) {
        float4 t = in4[i];
        float4 ww = w4[i];
        xo2[i*2 + 0] = __floats2half2_rn(t.x * r * ww.x, t.y * r * ww.y);
        xo2[i*2 + 1] = __floats2half2_rn(t.z * r * ww.z, t.w * r * ww.w);
    }
}

// ---------------- column mean over S, stage 1 (reads fp16 x) ---------------
__global__ void colsum_partial_kernel(int B, int S, int D)
{
    int g = blockIdx.x * blockDim.x + threadIdx.x;
    int total = PPART * B * D;
    if (g >= total) return;
    int d = g % D;
    int b = (g / D) % B;
    int p = g / (D * B);
    int chunk = S / PPART;
    long base = ((long)b * S + (long)p * chunk) * D + d;
    float s = 0.f;
    for (int i = 0; i < chunk; i++) s += __half2float(g_x[base + (long)i * D]);
    g_part[g] = s;
}

// ------- fused: colsum finalize + router logits + softmax (1 block) --------
__global__ void router_fused_kernel(const float* __restrict__ rw,
                                    int B, int S, int D, int E)
{
    __shared__ float sxm[BMAX * DMAX];      // 16 KB
    __shared__ float slog[BMAX * EMAX];
    int tid = threadIdx.x;                  // 1024 threads
    for (int i = tid; i < B * D; i += blockDim.x) {
        float s = 0.f;
        for (int p = 0; p < PPART; p++) s += g_part[p * B * D + i];
        sxm[i] = s / (float)S;
    }
    __syncthreads();
    int w = tid >> 5, lane = tid & 31;
    if (w < B * E) {
        int b = w / E, e = w % E;
        float s = 0.f;
        for (int d = lane; d < D; d += 32)
            s += sxm[b * D + d] * rw[(long)d * E + e];
        for (int o = 16; o > 0; o >>= 1) s += __shfl_xor_sync(0xffffffffu, s, o);
        if (lane == 0) slog[w] = s;
    }
    __syncthreads();
    if (tid < (unsigned)B) {
        int b = tid;
        float m = -1e30f;
        for (int e = 0; e < E; e++) m = fmaxf(m, slog[b * E + e]);
        float sum = 0.f, p[EMAX];
        for (int e = 0; e < E; e++) { p[e] = expf(slog[b * E + e] - m); sum += p[e]; }
        float inv = 1.f / sum;
        for (int e = 0; e < E; e++) g_probs[b * E + e] = p[e] * inv;
    }
}

// ------- expert mixing + transpose, all batches per tile load --------------
// w: [E][Dk][Dn] (n contiguous). dst: [B][Dn][Dk] (k contiguous, fp16).
// interleave!=0: output row n -> 2*(n%Dh) + n/Dh   (pairs hidden/gate cols)
__global__ void combineT_kernel(const float* __restrict__ w,
                                __half* __restrict__ dst,
                                int B, int E, int Dk, int Dn,
                                int interleave, int Dh)
{
    __shared__ float ts[32][33];
    __shared__ float sp[BMAX * EMAX];
    if (threadIdx.x < (unsigned)(B * E)) sp[threadIdx.x] = g_probs[threadIdx.x];
    __syncthreads();
    int k0 = blockIdx.x * 32, n0 = blockIdx.y * 32;
    int tk = threadIdx.x >> 3;        // 0..31
    int tn4 = threadIdx.x & 7;        // 0..7
    int tn = tk, tk4 = tn4;           // roles for write phase

    float4 t[EMAX];
    {
        const float* base = w + (long)(k0 + tk) * Dn + n0 + tn4 * 4;
        long estride = (long)Dk * Dn;
#pragma unroll
        for (int e = 0; e < EMAX; e++)
            t[e] = *(const float4*)(base + e * estride);
    }
    for (int b = 0; b < B; b++) {
        float4 acc = {0.f, 0.f, 0.f, 0.f};
#pragma unroll
        for (int e = 0; e < EMAX; e++) {
            float p = sp[b * EMAX + e];
            acc.x = fmaf(p, t[e].x, acc.x); acc.y = fmaf(p, t[e].y, acc.y);
            acc.z = fmaf(p, t[e].z, acc.z); acc.w = fmaf(p, t[e].w, acc.w);
        }
        ts[tk][tn4 * 4 + 0] = acc.x;
        ts[tk][tn4 * 4 + 1] = acc.y;
        ts[tk][tn4 * 4 + 2] = acc.z;
        ts[tk][tn4 * 4 + 3] = acc.w;
        __syncthreads();
        int nrow = n0 + tn;
        if (interleave) nrow = 2 * (nrow % Dh) + (nrow / Dh);
        __half2 h01 = __floats2half2_rn(ts[tk4 * 4 + 0][tn], ts[tk4 * 4 + 1][tn]);
        __half2 h23 = __floats2half2_rn(ts[tk4 * 4 + 2][tn], ts[tk4 * 4 + 3][tn]);
        __half2* dp = (__half2*)(dst + ((long)b * Dn + nrow) * Dk + k0 + tk4 * 4);
        dp[0] = h01;
        dp[1] = h23;
        __syncthreads();
    }
}

// ---------------- gating scalar ---------------------------------------------
__device__ __forceinline__ void cv_one(float hid, float gate, float& c, float& v)
{
    float t = __expf(-fabsf(gate));
    float r = rcp_fast(1.f + t);
    float sg, cc;
    if (gate >= 0.f) { sg = r;      cc = t * r; }
    else             { sg = t * r;  cc = r;     }
    float gg;
    if (hid >= 0.f) gg = hid + 0.5f;
    else {
        float t2 = __expf(hid);
        gg = t2 * rcp_fast(1.f + t2);
    }
    c = cc;
    v = sg * gg;
}

// ---------------- fp16 mma.sync GEMM, cp.async 3-stage, 2 CTAs/SM ----------
// A: [M][K] K-major fp16.  Bt: [N][K] K-major fp16.  fp32 accumulate.
// CTA tile 128x128, 8 warps (2x4) of 64x32. BK=64 (rows = 128 bytes).
// MODE 0: Cout = A@Bt^T + resid (fp32).  MODE 1: (hidden,gate)->(c,v) pairs.
#define STAGES 3
#define CTA_M 128
#define CTA_N 128
#define GBK 64
#define A_BYTES (CTA_M * GBK * 2)                 // 16384
#define B_BYTES (CTA_N * GBK * 2)                 // 16384
#define STAGE_BYTES (A_BYTES + B_BYTES)           // 32768
#define GEMM_SMEM (STAGES * STAGE_BYTES + 1024)   // ~97.3 KB

template<int MODE>
__global__ void __launch_bounds__(256, 2)
tc_gemm(const __half* __restrict__ A, const __half* __restrict__ Bt,
        const float* __restrict__ resid, float* __restrict__ Cout,
        float2* __restrict__ cv,
        int M, int N, int K, long sA, long sB, long sC, int Dh, int S)
{
    extern __shared__ char dsm[];
    const uint32_t sb = (smem_u32(dsm) + 1023u) & ~1023u;

    const int bz = blockIdx.z;
    A  += (long)bz * sA;
    Bt += (long)bz * sB;

    const long tileM = (long)blockIdx.y * CTA_M;
    const long tileN = (long)blockIdx.x * CTA_N;
    const int tid  = threadIdx.x;
    const int warp = tid >> 5;
    const int lane = tid & 31;
    const int wm = (warp >> 2) * 64;   // 0,64
    const int wn = (warp & 3) * 32;    // 0..96
    const int grp = lane >> 2;         // 0..7
    const int tig = lane & 3;          // 0..3

    float acc[4][4][4];
#pragma unroll
    for (int i = 0; i < 4; i++)
#pragma unroll
        for (int j = 0; j < 4; j++)
#pragma unroll
            for (int r = 0; r < 4; r++) acc[i][j][r] = 0.f;

    auto fill_stage = [&](int stage, int ch) {
        uint32_t bAf = sb + stage * STAGE_BYTES;
        uint32_t bBf = bAf + A_BYTES;
        int k0 = ch * GBK;
#pragma unroll
        for (int j = 0; j < 4; j++) {
            int idx = j * 256 + tid;
            int row = idx >> 3, seg = idx & 7;
            uint32_t off = (uint32_t)(row * 128) + (uint32_t)((seg * 16) ^ ((row & 7) * 16));
            cp16(bAf + off, A + (tileM + row) * K + k0 + seg * 8);
        }
#pragma unroll
        for (int j = 0; j < 4; j++) {
            int idx = j * 256 + tid;
            int row = idx >> 3, seg = idx & 7;
            uint32_t off = (uint32_t)(row * 128) + (uint32_t)((seg * 16) ^ ((row & 7) * 16));
            cp16(bBf + off, Bt + (tileN + row) * K + k0 + seg * 8);
        }
        asm volatile("cp.async.commit_group;" ::: "memory");
    };

    const int nch = K / GBK;
    fill_stage(0, 0);
    fill_stage(1, 1);

    for (int ch = 0; ch < nch; ch++) {
        int st = ch % STAGES;
        asm volatile("cp.async.wait_group %0;" :: "n"(STAGES - 2) : "memory");
        __syncthreads();
        if (ch + 2 < nch) fill_stage((ch + 2) % STAGES, ch + 2);
        else asm volatile("cp.async.commit_group;" ::: "memory");

        uint32_t bA = sb + st * STAGE_BYTES;
        uint32_t bB = bA + A_BYTES;
        uint32_t aRB0[4], aRB1[4], aMK[4];
#pragma unroll
        for (int mf = 0; mf < 4; mf++) {
            int m0 = wm + mf * 16 + grp;
            aRB0[mf] = bA + m0 * 128;
            aRB1[mf] = bA + (m0 + 8) * 128;
            aMK[mf] = (uint32_t)((m0 & 7) * 16);
        }
        uint32_t bRB[4], bMK[4];
#pragma unroll
        for (int nf = 0; nf < 4; nf++) {
            int n0 = wn + nf * 8 + grp;
            bRB[nf] = bB + n0 * 128;
            bMK[nf] = (uint32_t)((n0 & 7) * 16);
        }
#pragma unroll
        for (int ks = 0; ks < 4; ks++) {
            uint32_t klo = (uint32_t)(ks * 32 + tig * 4);
            uint32_t khi = klo + 16;
            uint32_t af[4][4];
#pragma unroll
            for (int mf = 0; mf < 4; mf++) {
                af[mf][0] = lds32(aRB0[mf] + (klo ^ aMK[mf]));
                af[mf][1] = lds32(aRB1[mf] + (klo ^ aMK[mf]));
                af[mf][2] = lds32(aRB0[mf] + (khi ^ aMK[mf]));
                af[mf][3] = lds32(aRB1[mf] + (khi ^ aMK[mf]));
            }
            uint32_t bf[4][2];
#pragma unroll
            for (int nf = 0; nf < 4; nf++) {
                bf[nf][0] = lds32(bRB[nf] + (klo ^ bMK[nf]));
                bf[nf][1] = lds32(bRB[nf] + (khi ^ bMK[nf]));
            }
#pragma unroll
            for (int mf = 0; mf < 4; mf++)
#pragma unroll
                for (int nf = 0; nf < 4; nf++) {
                    asm volatile(
                        "mma.sync.aligned.m16n8k16.row.col.f32.f16.f16.f32 "
                        "{%0,%1,%2,%3},{%4,%5,%6,%7},{%8,%9},{%0,%1,%2,%3};"
                        : "+f"(acc[mf][nf][0]), "+f"(acc[mf][nf][1]),
                          "+f"(acc[mf][nf][2]), "+f"(acc[mf][nf][3])
                        : "r"(af[mf][0]), "r"(af[mf][1]), "r"(af[mf][2]), "r"(af[mf][3]),
                          "r"(bf[nf][0]), "r"(bf[nf][1]));
                }
        }
    }

    // ---- epilogue ----
    if (MODE == 0) {
        const float* rz = resid ? resid + (long)bz * sC : nullptr;
        float* czp = Cout + (long)bz * sC;
#pragma unroll
        for (int mf = 0; mf < 4; mf++) {
#pragma unroll
            for (int nf = 0; nf < 4; nf++) {
                long r0 = tileM + wm + mf * 16 + grp;
                long c  = tileN + wn + nf * 8 + 2 * tig;
                long i0 = r0 * N + c;
                long i1 = (r0 + 8) * N + c;
                float2 v0 = make_float2(acc[mf][nf][0], acc[mf][nf][1]);
                float2 v1 = make_float2(acc[mf][nf][2], acc[mf][nf][3]);
                if (rz) {
                    float2 q0 = *(const float2*)(rz + i0);
                    float2 q1 = *(const float2*)(rz + i1);
                    v0.x += q0.x; v0.y += q0.y;
                    v1.x += q1.x; v1.y += q1.y;
                }
                *(float2*)(czp + i0) = v0;
                *(float2*)(czp + i1) = v1;
            }
        }
    } else {
        float2* cvb = cv + (long)bz * S * (long)Dh;
#pragma unroll
        for (int mf = 0; mf < 4; mf++) {
#pragma unroll
            for (int nf = 0; nf < 4; nf++) {
                long r0 = tileM + wm + mf * 16 + grp;
                long c  = tileN + wn + nf * 8 + 2 * tig;
                long d  = c >> 1;
                float cc, vv;
                cv_one(acc[mf][nf][0], acc[mf][nf][1], cc, vv);
                cvb[r0 * Dh + d] = make_float2(cc, vv);
                cv_one(acc[mf][nf][2], acc[mf][nf][3], cc, vv);
                cvb[(r0 + 8) * Dh + d] = make_float2(cc, vv);
            }
        }
    }
}

// ---------------- chunked linear-recurrence scan ---------------------------
__global__ void scan_passA_kernel(int B, int S, int D, int L, int nch)
{
    int g = blockIdx.x * blockDim.x + threadIdx.x;
    int total = B * nch * D;
    if (g >= total) return;
    int d = g % D;
    int ch = (g / D) % nch;
    int b = g / (D * nch);
    const float2* cv = (const float2*)g_hg;
    long base = ((long)b * S + (long)ch * L) * D + d;
    float A = 1.f, Y = 0.f;
    for (int i = 0; i < L; i++) {
        float2 t = cv[base + (long)i * D];
        A *= t.x;
        Y = fmaf(t.x, Y, t.y);
    }
    g_Ach[g] = A;
    g_Ych[g] = Y;
}

__global__ void scan_passB_kernel(const float* __restrict__ state,
                                  float* __restrict__ out,
                                  int B, int D, int nch,
                                  long outBase, long out_size)
{
    int g = blockIdx.x * blockDim.x + threadIdx.x;
    if (g >= B * D) return;
    int d = g % D, b = g / D;
    float h = state[b * D + d];
    for (int ch = 0; ch < nch; ch++) {
        int idx = (b * nch + ch) * D + d;
        g_hin[idx] = h;
        h = fmaf(g_Ach[idx], h, g_Ych[idx]);
    }
    if (out_size >= outBase + (long)B * D)
        out[outBase + (long)b * D + d] = h;          // new_state
    if (g == 0 && out_size >= outBase + (long)B * D + 1)
        out[outBase + (long)B * D] = 0.f;            // aux_loss
}

__global__ void scan_passC_kernel(int B, int S, int D, int L, int nch)
{
    int g = blockIdx.x * blockDim.x + threadIdx.x;
    int total = B * nch * D;
    if (g >= total) return;
    int d = g % D;
    int ch = (g / D) % nch;
    int b = g / (D * nch);
    const float2* cv = (const float2*)g_hg;
    long base = ((long)b * S + (long)ch * L) * D + d;
    float h = g_hin[g];
    for (int i = 0; i < L; i++) {
        float2 t = cv[base + (long)i * D];
        h = fmaf(t.x, h, t.y);
        g_h[base + (long)i * D] = __float2half_rn(h);
    }
}

// ---------------- launch ----------------------------------------------------
extern "C" void kernel_launch(void* const* d_in, const int* in_sizes, int n_in,
                              void* d_out, int out_size)
{
    const float* inputs   = (const float*)d_in[0];
    // d_in[1]: attention_mask (unused by reference)
    const float* state    = (const float*)d_in[2];
    const float* normw    = (const float*)d_in[3];
    const float* router_w = (const float*)d_in[4];
    const float* w_in     = (const float*)d_in[5];
    const float* w_out    = (const float*)d_in[6];
    float* out = (float*)d_out;

    const int D = in_sizes[3];
    const int E = in_sizes[4] / D;
    const int B = in_sizes[2] / D;
    const int S = in_sizes[0] / (B * D);
    const int N2 = 2 * D;
    const int L = S / NCH;

    __half *px, *ph, *pWi, *pWo;
    float *phg;
    cudaGetSymbolAddress((void**)&px,  g_x);
    cudaGetSymbolAddress((void**)&phg, g_hg);
    cudaGetSymbolAddress((void**)&ph,  g_h);
    cudaGetSymbolAddress((void**)&pWi, g_Wi);
    cudaGetSymbolAddress((void**)&pWo, g_Wo);

    cudaFuncSetAttribute(tc_gemm<0>, cudaFuncAttributeMaxDynamicSharedMemorySize, GEMM_SMEM);
    cudaFuncSetAttribute(tc_gemm<1>, cudaFuncAttributeMaxDynamicSharedMemorySize, GEMM_SMEM);

    // 1. RMSNorm (fp16 output)
    rmsnorm_kernel<<<B * S, 256>>>(inputs, normw, D);

    // 2. column partial sums
    {
        int total = PPART * B * D;
        colsum_partial_kernel<<<(total + 255) / 256, 256>>>(B, S, D);
    }

    // 3. fused colsum-final + router softmax
    router_fused_kernel<<<1, 1024>>>(router_w, B, S, D, E);

    // 4. expert-mixed transposed weights (fp16, all batches per tile)
    {
        dim3 gI(D / 32, N2 / 32);
        combineT_kernel<<<gI, 256>>>(w_in, pWi, B, E, D, N2, 1, D);   // interleaved
        dim3 gO(D / 32, D / 32);
        combineT_kernel<<<gO, 256>>>(w_out, pWo, B, E, D, D, 0, D);
    }

    // 5. GEMM1 (M=S, N=2D, K=D) with fused gating -> (c,v) pairs in g_hg
    {
        dim3 grid(N2 / CTA_N, S / CTA_M, B);
        tc_gemm<1><<<grid, 256, GEMM_SMEM>>>(px, pWi, nullptr, nullptr,
                                             (float2*)phg,
                                             S, N2, D,
                                             (long)S * D, (long)N2 * D, 0L,
                                             D, S);
    }

    // 6. chunked scan
    {
        int totA = B * NCH * D;
        scan_passA_kernel<<<(totA + 255) / 256, 256>>>(B, S, D, L, NCH);
        scan_passB_kernel<<<(B * D + 255) / 256, 256>>>(state, out, B, D, NCH,
                                                        (long)B * S * D, (long)out_size);
        scan_passC_kernel<<<(totA + 255) / 256, 256>>>(B, S, D, L, NCH);
    }

    // 7. GEMM2: out = h @ Wo^T + inputs   (M=S, N=D, K=D)
    {
        dim3 grid(D / CTA_N, S / CTA_M, B);
        tc_gemm<0><<<grid, 256, GEMM_SMEM>>>(ph, pWo, inputs, out,
                                             nullptr,
                                             S, D, D,
                                             (long)S * D, (long)D * D, (long)S * D,
                                             D, S);
    }
}